// round 8
// baseline (speedup 1.0000x reference)
#include <cuda_runtime.h>
#include <cuda_bf16.h>
#include <cstdint>

#define BATCH 2
#define SEQ   2048
#define EMB   1024
#define NH    16
#define HD    64
#define MROWS (BATCH*SEQ)   // 4096

// ---------------------------------------------------------------------------
// Scratch (static device globals — allocation guards forbid cudaMalloc)
// ---------------------------------------------------------------------------
__device__ __nv_bfloat16 g_qh[MROWS * EMB], g_ql[MROWS * EMB];
__device__ __nv_bfloat16 g_kh[MROWS * EMB], g_kl[MROWS * EMB];
__device__ __nv_bfloat16 g_vh[MROWS * EMB], g_vl[MROWS * EMB];
__device__ __nv_bfloat16 g_qph[MROWS * EMB], g_qpl[MROWS * EMB];
__device__ __nv_bfloat16 g_kph[MROWS * EMB], g_kpl[MROWS * EMB];
__device__ __nv_bfloat16 g_vph[MROWS * EMB], g_vpl[MROWS * EMB];
__device__ __nv_bfloat16 g_vth[MROWS * EMB], g_vtl[MROWS * EMB];
__device__ __nv_bfloat16 g_ch[MROWS * EMB], g_cl[MROWS * EMB];
__device__ __nv_bfloat16 g_wqh[EMB * EMB], g_wql[EMB * EMB];
__device__ __nv_bfloat16 g_wkh[EMB * EMB], g_wkl[EMB * EMB];
__device__ __nv_bfloat16 g_wvh[EMB * EMB], g_wvl[EMB * EMB];
__device__ __nv_bfloat16 g_woh[EMB * EMB], g_wol[EMB * EMB];

// ---------------------------------------------------------------------------
// Helpers
// ---------------------------------------------------------------------------
__device__ __forceinline__ uint32_t smem_u32(const void* p) {
    uint32_t a;
    asm("{ .reg .u64 t; cvta.to.shared.u64 t, %1; cvt.u32.u64 %0, t; }" : "=r"(a) : "l"(p));
    return a;
}

#define CP_ASYNC16(dst, src) \
    asm volatile("cp.async.cg.shared.global [%0], [%1], 16;" :: "r"((uint32_t)(dst)), "l"(src))
#define CP_COMMIT() asm volatile("cp.async.commit_group;" ::: "memory")
#define CP_WAIT0()  asm volatile("cp.async.wait_group 0;" ::: "memory")
#define CP_WAIT1()  asm volatile("cp.async.wait_group 1;" ::: "memory")

__device__ __forceinline__ void mma16816(float* c, const uint32_t* a, const uint32_t* b) {
    asm volatile(
        "mma.sync.aligned.m16n8k16.row.col.f32.bf16.bf16.f32 "
        "{%0,%1,%2,%3}, {%4,%5,%6,%7}, {%8,%9}, {%0,%1,%2,%3};"
        : "+f"(c[0]), "+f"(c[1]), "+f"(c[2]), "+f"(c[3])
        : "r"(a[0]), "r"(a[1]), "r"(a[2]), "r"(a[3]), "r"(b[0]), "r"(b[1]));
}

__device__ __forceinline__ void split1(float x, __nv_bfloat16& h, __nv_bfloat16& l) {
    h = __float2bfloat16_rn(x);
    l = __float2bfloat16_rn(x - __bfloat162float(h));
}
__device__ __forceinline__ uint32_t pack2(__nv_bfloat16 a, __nv_bfloat16 b) {
    return (uint32_t)__bfloat16_as_ushort(a) | ((uint32_t)__bfloat16_as_ushort(b) << 16);
}
__device__ __forceinline__ void split_pack2(float x0, float x1, uint32_t& hi, uint32_t& lo) {
    __nv_bfloat16 h0, l0, h1, l1;
    split1(x0, h0, l0); split1(x1, h1, l1);
    hi = pack2(h0, h1); lo = pack2(l0, l1);
}

// ---------------------------------------------------------------------------
// Pre-pass 1: elementwise bf16 hi/lo split
// ---------------------------------------------------------------------------
__global__ void split_bf16(const float* __restrict__ x, __nv_bfloat16* __restrict__ hi,
                           __nv_bfloat16* __restrict__ lo, int n4) {
    int i = blockIdx.x * blockDim.x + threadIdx.x;
    if (i >= n4) return;
    float4 v = ((const float4*)x)[i];
    uint32_t h01, l01, h23, l23;
    split_pack2(v.x, v.y, h01, l01);
    split_pack2(v.z, v.w, h23, l23);
    ((uint2*)hi)[i] = make_uint2(h01, h23);
    ((uint2*)lo)[i] = make_uint2(l01, l23);
}

// ---------------------------------------------------------------------------
// Pre-pass 2: W[K][N] -> Wt hi/lo [N][K], bf16
// ---------------------------------------------------------------------------
__global__ void transpose_split(const float* __restrict__ W,
                                __nv_bfloat16* __restrict__ Thi,
                                __nv_bfloat16* __restrict__ Tlo) {
    __shared__ float t[32][33];
    int x = blockIdx.x * 32 + threadIdx.x;
    int y = blockIdx.y * 32 + threadIdx.y;
    #pragma unroll
    for (int i = 0; i < 32; i += 8)
        t[threadIdx.y + i][threadIdx.x] = W[(size_t)(y + i) * EMB + x];
    __syncthreads();
    int nx = blockIdx.y * 32 + threadIdx.x;
    int ny = blockIdx.x * 32 + threadIdx.y;
    #pragma unroll
    for (int i = 0; i < 32; i += 8) {
        float v = t[threadIdx.x][threadIdx.y + i];
        __nv_bfloat16 h, l;
        split1(v, h, l);
        Thi[(size_t)(ny + i) * EMB + nx] = h;
        Tlo[(size_t)(ny + i) * EMB + nx] = l;
    }
}

// ---------------------------------------------------------------------------
// V transpose: [b*S+s][h*64+d] -> [(b*16+h)*64+d][s]
// ---------------------------------------------------------------------------
__global__ void transpose_v(const __nv_bfloat16* __restrict__ vh,
                            const __nv_bfloat16* __restrict__ vl,
                            __nv_bfloat16* __restrict__ th,
                            __nv_bfloat16* __restrict__ tl) {
    __shared__ __nv_bfloat16 a[32][33], c[32][33];
    const int bh = blockIdx.z;
    const int b = bh >> 4, h = bh & 15;
    const int s0 = blockIdx.x * 32, d0 = blockIdx.y * 32;
    const int tx = threadIdx.x, ty = threadIdx.y;
    #pragma unroll
    for (int i = 0; i < 32; i += 8) {
        size_t src = (size_t)(b * SEQ + s0 + ty + i) * EMB + h * HD + d0 + tx;
        a[ty + i][tx] = vh[src];
        c[ty + i][tx] = vl[src];
    }
    __syncthreads();
    #pragma unroll
    for (int i = 0; i < 32; i += 8) {
        size_t dst = (size_t)(bh * HD + d0 + ty + i) * SEQ + s0 + tx;
        th[dst] = a[tx][ty + i];
        tl[dst] = c[tx][ty + i];
    }
}

// ---------------------------------------------------------------------------
// mma.sync 3x-bf16 GEMM, 2-stage pipelined. Block 128x128, BK=16, 256 thr.
// SMEM: 2 stages x 4 tiles x 128 rows x 12 words = 49152 B static (==48KB).
// TW=12: frag-read banks 12g+t mod 32 all distinct (conflict-free).
// ---------------------------------------------------------------------------
#define TW 12
#define TILE_W (128 * TW)    // 1536 words

__global__ __launch_bounds__(256) void gemm_bf16x3(
    const __nv_bfloat16* __restrict__ Ahi, const __nv_bfloat16* __restrict__ Alo,
    const __nv_bfloat16* __restrict__ Bhi, const __nv_bfloat16* __restrict__ Blo,
    float* __restrict__ Cf, __nv_bfloat16* __restrict__ Chi,
    __nv_bfloat16* __restrict__ Clo, float scale, int M, int N, int K)
{
    __shared__ uint32_t sm[8 * TILE_W];   // 49152 bytes, static
    const int tid = threadIdx.x;
    const int wid = tid >> 5, lane = tid & 31;
    const int g = lane >> 2, t = lane & 3;
    const int wm = wid & 1, wn = wid >> 1;
    const int bm = blockIdx.y * 128, bn = blockIdx.x * 128;

    const uint32_t sbase = smem_u32(sm);
    const int r0 = tid >> 1, c0 = tid & 1;   // 128 rows x 2 chunks of 16B
    const __nv_bfloat16* gsrc[4] = {
        Ahi + (size_t)bm * K, Alo + (size_t)bm * K,
        Bhi + (size_t)bn * K, Blo + (size_t)bn * K
    };

    float acc[4][4][4] = {};

    auto issue = [&](int stage, int k0) {
        #pragma unroll
        for (int tile = 0; tile < 4; tile++) {
            const __nv_bfloat16* src = gsrc[tile] + (size_t)r0 * K + k0 + c0 * 8;
            uint32_t d = sbase + ((stage * 4 + tile) * TILE_W + r0 * TW + c0 * 4) * 4;
            CP_ASYNC16(d, src);
        }
    };

    const int NS = K / 16;
    issue(0, 0);
    CP_COMMIT();

    for (int s = 0; s < NS; s++) {
        if (s + 1 < NS) {
            issue((s + 1) & 1, (s + 1) * 16);
            CP_COMMIT();
            CP_WAIT1();
        } else {
            CP_WAIT0();
        }
        __syncthreads();

        const uint32_t* As  = sm + ((s & 1) * 4 + 0) * TILE_W;
        const uint32_t* Als = sm + ((s & 1) * 4 + 1) * TILE_W;
        const uint32_t* Bs  = sm + ((s & 1) * 4 + 2) * TILE_W;
        const uint32_t* Bls = sm + ((s & 1) * 4 + 3) * TILE_W;

        uint32_t ah[4][4], al[4][4], bh[4][2], bl[4][2];
        #pragma unroll
        for (int mf = 0; mf < 4; mf++) {
            const int m0 = wm * 64 + mf * 16;
            const int i0 = (m0 + g) * TW + t;
            const int i8 = (m0 + g + 8) * TW + t;
            ah[mf][0] = As[i0];  ah[mf][1] = As[i8];
            ah[mf][2] = As[i0 + 4]; ah[mf][3] = As[i8 + 4];
            al[mf][0] = Als[i0]; al[mf][1] = Als[i8];
            al[mf][2] = Als[i0 + 4]; al[mf][3] = Als[i8 + 4];
        }
        #pragma unroll
        for (int nf = 0; nf < 4; nf++) {
            const int n0 = wn * 32 + nf * 8;
            const int j0 = (n0 + g) * TW + t;
            bh[nf][0] = Bs[j0];  bh[nf][1] = Bs[j0 + 4];
            bl[nf][0] = Bls[j0]; bl[nf][1] = Bls[j0 + 4];
        }
        #pragma unroll
        for (int mf = 0; mf < 4; mf++)
            #pragma unroll
            for (int nf = 0; nf < 4; nf++) {
                mma16816(acc[mf][nf], ah[mf], bh[nf]);
                mma16816(acc[mf][nf], ah[mf], bl[nf]);
                mma16816(acc[mf][nf], al[mf], bh[nf]);
            }
        __syncthreads();
    }

    #pragma unroll
    for (int mf = 0; mf < 4; mf++) {
        const int m = bm + wm * 64 + mf * 16 + g;
        #pragma unroll
        for (int nf = 0; nf < 4; nf++) {
            const int n = bn + wn * 32 + nf * 8 + 2 * t;
            float v0 = acc[mf][nf][0], v1 = acc[mf][nf][1];
            float v2 = acc[mf][nf][2], v3 = acc[mf][nf][3];
            if (Cf) {
                *(float2*)(Cf + (size_t)m * N + n)       = make_float2(v0, v1);
                *(float2*)(Cf + (size_t)(m + 8) * N + n) = make_float2(v2, v3);
            }
            if (Chi) {
                uint32_t h01, l01, h23, l23;
                split_pack2(v0 * scale, v1 * scale, h01, l01);
                split_pack2(v2 * scale, v3 * scale, h23, l23);
                *(uint32_t*)(Chi + (size_t)m * N + n)       = h01;
                *(uint32_t*)(Clo + (size_t)m * N + n)       = l01;
                *(uint32_t*)(Chi + (size_t)(m + 8) * N + n) = h23;
                *(uint32_t*)(Clo + (size_t)(m + 8) * N + n) = l23;
            }
        }
    }
}

// ---------------------------------------------------------------------------
// Flash attention on mma.sync, 2-stage pipelined K/V. Block = 64 queries,
// 4 warps. KV tile = 32. SMEM: 2 x (K 9216 + V 10240) = 38912 B static.
// ---------------------------------------------------------------------------
#define FKP 72
#define FVP 40

__global__ __launch_bounds__(128) void flash_mma(
    const __nv_bfloat16* __restrict__ Qh, const __nv_bfloat16* __restrict__ Ql,
    const __nv_bfloat16* __restrict__ Kh, const __nv_bfloat16* __restrict__ Kl,
    const __nv_bfloat16* __restrict__ Vth, const __nv_bfloat16* __restrict__ Vtl,
    __nv_bfloat16* __restrict__ Ch, __nv_bfloat16* __restrict__ Cl)
{
    __shared__ __nv_bfloat16 Ksh[2][32 * FKP], Ksl[2][32 * FKP];
    __shared__ __nv_bfloat16 Vsh[2][64 * FVP], Vsl[2][64 * FVP];

    const int tid = threadIdx.x, wid = tid >> 5, lane = tid & 31;
    const int g = lane >> 2, t = lane & 3;
    const int qt = blockIdx.x, h = blockIdx.y, b = blockIdx.z;
    const int q0 = qt * 64, m0 = wid * 16;

    // Q fragments from global (pre-scaled by 1/8)
    uint32_t qhf[4][4], qlf[4][4];
    {
        const size_t rbase = (size_t)(b * SEQ + q0 + m0 + g) * EMB + h * HD;
        const __nv_bfloat16* q0h = Qh + rbase;
        const __nv_bfloat16* q8h = q0h + (size_t)8 * EMB;
        const __nv_bfloat16* q0l = Ql + rbase;
        const __nv_bfloat16* q8l = q0l + (size_t)8 * EMB;
        #pragma unroll
        for (int kc = 0; kc < 4; kc++) {
            const int d0 = kc * 16 + 2 * t;
            qhf[kc][0] = *(const uint32_t*)(q0h + d0);
            qhf[kc][1] = *(const uint32_t*)(q8h + d0);
            qhf[kc][2] = *(const uint32_t*)(q0h + d0 + 8);
            qhf[kc][3] = *(const uint32_t*)(q8h + d0 + 8);
            qlf[kc][0] = *(const uint32_t*)(q0l + d0);
            qlf[kc][1] = *(const uint32_t*)(q8l + d0);
            qlf[kc][2] = *(const uint32_t*)(q0l + d0 + 8);
            qlf[kc][3] = *(const uint32_t*)(q8l + d0 + 8);
        }
    }

    float O[8][4] = {};
    float m_g = -1e30f, m_g8 = -1e30f, l_g = 0.f, l_g8 = 0.f;

    const int kr = tid >> 2, kc4 = tid & 3;
    const int vd = tid >> 1, vc = tid & 1;
    const __nv_bfloat16* khb = Kh + (size_t)(b * SEQ) * EMB + h * HD;
    const __nv_bfloat16* klb = Kl + (size_t)(b * SEQ) * EMB + h * HD;
    const __nv_bfloat16* vhb = Vth + (size_t)((b * NH + h) * HD) * SEQ;
    const __nv_bfloat16* vlb = Vtl + (size_t)((b * NH + h) * HD) * SEQ;

    auto issueKV = [&](int st, int j0) {
        const __nv_bfloat16* ks = khb + (size_t)(j0 + kr) * EMB + kc4 * 8;
        const __nv_bfloat16* ls = klb + (size_t)(j0 + kr) * EMB + kc4 * 8;
        const uint32_t kd = kr * (FKP * 2) + kc4 * 16;
        const uint32_t sKh = smem_u32(Ksh[st]), sKl = smem_u32(Ksl[st]);
        CP_ASYNC16(sKh + kd, ks);
        CP_ASYNC16(sKh + kd + 64, ks + 32);
        CP_ASYNC16(sKl + kd, ls);
        CP_ASYNC16(sKl + kd + 64, ls + 32);
        const __nv_bfloat16* vs = vhb + (size_t)vd * SEQ + j0 + vc * 8;
        const __nv_bfloat16* ws = vlb + (size_t)vd * SEQ + j0 + vc * 8;
        const uint32_t vdd = vd * (FVP * 2) + vc * 16;
        const uint32_t sVh = smem_u32(Vsh[st]), sVl = smem_u32(Vsl[st]);
        CP_ASYNC16(sVh + vdd, vs);
        CP_ASYNC16(sVh + vdd + 32, vs + 16);
        CP_ASYNC16(sVl + vdd, ws);
        CP_ASYNC16(sVl + vdd + 32, ws + 16);
    };

    issueKV(0, 0);
    CP_COMMIT();

    for (int it = 0; it < SEQ / 32; it++) {
        const int st = it & 1;
        if (it + 1 < SEQ / 32) {
            issueKV(st ^ 1, (it + 1) * 32);
            CP_COMMIT();
            CP_WAIT1();
        } else {
            CP_WAIT0();
        }
        __syncthreads();

        const __nv_bfloat16* Kh_s = Ksh[st];
        const __nv_bfloat16* Kl_s = Ksl[st];
        const __nv_bfloat16* Vh_s = Vsh[st];
        const __nv_bfloat16* Vl_s = Vsl[st];

        // S = Q K^T
        float s[4][4] = {};
        #pragma unroll
        for (int kc = 0; kc < 4; kc++) {
            uint32_t bh_[4][2], bl_[4][2];
            #pragma unroll
            for (int nf = 0; nf < 4; nf++) {
                const int base = (nf * 8 + g) * FKP + kc * 16 + 2 * t;
                bh_[nf][0] = *(const uint32_t*)(Kh_s + base);
                bh_[nf][1] = *(const uint32_t*)(Kh_s + base + 8);
                bl_[nf][0] = *(const uint32_t*)(Kl_s + base);
                bl_[nf][1] = *(const uint32_t*)(Kl_s + base + 8);
            }
            #pragma unroll
            for (int nf = 0; nf < 4; nf++) {
                mma16816(s[nf], qhf[kc], bh_[nf]);
                mma16816(s[nf], qhf[kc], bl_[nf]);
                mma16816(s[nf], qlf[kc], bh_[nf]);
            }
        }

        // online softmax (rows g and g+8)
        float mx0 = -1e30f, mx8 = -1e30f;
        #pragma unroll
        for (int nf = 0; nf < 4; nf++) {
            mx0 = fmaxf(mx0, fmaxf(s[nf][0], s[nf][1]));
            mx8 = fmaxf(mx8, fmaxf(s[nf][2], s[nf][3]));
        }
        mx0 = fmaxf(mx0, __shfl_xor_sync(0xffffffffu, mx0, 1));
        mx0 = fmaxf(mx0, __shfl_xor_sync(0xffffffffu, mx0, 2));
        mx8 = fmaxf(mx8, __shfl_xor_sync(0xffffffffu, mx8, 1));
        mx8 = fmaxf(mx8, __shfl_xor_sync(0xffffffffu, mx8, 2));
        const float mn_g = fmaxf(m_g, mx0), mn_g8 = fmaxf(m_g8, mx8);
        const float alpha_g = __expf(m_g - mn_g), alpha_g8 = __expf(m_g8 - mn_g8);
        m_g = mn_g; m_g8 = mn_g8;

        float p[4][4];
        float sum0 = 0.f, sum8 = 0.f;
        #pragma unroll
        for (int nf = 0; nf < 4; nf++) {
            p[nf][0] = __expf(s[nf][0] - mn_g);
            p[nf][1] = __expf(s[nf][1] - mn_g);
            p[nf][2] = __expf(s[nf][2] - mn_g8);
            p[nf][3] = __expf(s[nf][3] - mn_g8);
            sum0 += p[nf][0] + p[nf][1];
            sum8 += p[nf][2] + p[nf][3];
        }
        sum0 += __shfl_xor_sync(0xffffffffu, sum0, 1);
        sum0 += __shfl_xor_sync(0xffffffffu, sum0, 2);
        sum8 += __shfl_xor_sync(0xffffffffu, sum8, 1);
        sum8 += __shfl_xor_sync(0xffffffffu, sum8, 2);
        l_g  = l_g  * alpha_g  + sum0;
        l_g8 = l_g8 * alpha_g8 + sum8;

        #pragma unroll
        for (int nf2 = 0; nf2 < 8; nf2++) {
            O[nf2][0] *= alpha_g;  O[nf2][1] *= alpha_g;
            O[nf2][2] *= alpha_g8; O[nf2][3] *= alpha_g8;
        }

        // P fragments (S C-frag == PV A-frag layout)
        uint32_t pah[2][4], pal[2][4];
        #pragma unroll
        for (int kc2 = 0; kc2 < 2; kc2++) {
            const int nA = 2 * kc2, nB = 2 * kc2 + 1;
            split_pack2(p[nA][0], p[nA][1], pah[kc2][0], pal[kc2][0]);
            split_pack2(p[nA][2], p[nA][3], pah[kc2][1], pal[kc2][1]);
            split_pack2(p[nB][0], p[nB][1], pah[kc2][2], pal[kc2][2]);
            split_pack2(p[nB][2], p[nB][3], pah[kc2][3], pal[kc2][3]);
        }

        // O += P V
        #pragma unroll
        for (int nf2 = 0; nf2 < 8; nf2++) {
            #pragma unroll
            for (int kc2 = 0; kc2 < 2; kc2++) {
                const int base = (nf2 * 8 + g) * FVP + kc2 * 16 + 2 * t;
                uint32_t vbh[2], vbl[2];
                vbh[0] = *(const uint32_t*)(Vh_s + base);
                vbh[1] = *(const uint32_t*)(Vh_s + base + 8);
                vbl[0] = *(const uint32_t*)(Vl_s + base);
                vbl[1] = *(const uint32_t*)(Vl_s + base + 8);
                mma16816(O[nf2], pah[kc2], vbh);
                mma16816(O[nf2], pal[kc2], vbh);
                mma16816(O[nf2], pah[kc2], vbl);
            }
        }
        __syncthreads();   // all reads done before this stage is re-filled
    }

    // epilogue: normalize, split to bf16 hi/lo
    const float li_g = 1.0f / l_g, li_g8 = 1.0f / l_g8;
    const size_t row0 = (size_t)(b * SEQ + q0 + m0 + g) * EMB;
    const size_t row8 = row0 + (size_t)8 * EMB;
    #pragma unroll
    for (int nf2 = 0; nf2 < 8; nf2++) {
        const int col = h * HD + nf2 * 8 + 2 * t;
        uint32_t h01, l01, h23, l23;
        split_pack2(O[nf2][0] * li_g,  O[nf2][1] * li_g,  h01, l01);
        split_pack2(O[nf2][2] * li_g8, O[nf2][3] * li_g8, h23, l23);
        *(uint32_t*)(Ch + row0 + col) = h01;
        *(uint32_t*)(Cl + row0 + col) = l01;
        *(uint32_t*)(Ch + row8 + col) = h23;
        *(uint32_t*)(Cl + row8 + col) = l23;
    }
}

// ---------------------------------------------------------------------------
extern "C" void kernel_launch(void* const* d_in, const int* in_sizes, int n_in,
                              void* d_out, int out_size)
{
    const float* Q  = (const float*)d_in[0];
    const float* K  = (const float*)d_in[1];
    const float* V  = (const float*)d_in[2];
    const float* Wq = (const float*)d_in[3];
    const float* Wk = (const float*)d_in[4];
    const float* Wv = (const float*)d_in[5];
    const float* Wo = (const float*)d_in[6];
    float* out = (float*)d_out;

    static __nv_bfloat16 *qh, *ql, *kh, *kl, *vh, *vl;
    static __nv_bfloat16 *qph, *qpl, *kph, *kpl, *vph, *vpl, *vth, *vtl, *ch, *cl;
    static __nv_bfloat16 *wqh, *wql, *wkh, *wkl, *wvh, *wvl, *woh, *wol;
    static bool inited = false;
    if (!inited) {
        inited = true;
        cudaGetSymbolAddress((void**)&qh,  g_qh);  cudaGetSymbolAddress((void**)&ql,  g_ql);
        cudaGetSymbolAddress((void**)&kh,  g_kh);  cudaGetSymbolAddress((void**)&kl,  g_kl);
        cudaGetSymbolAddress((void**)&vh,  g_vh);  cudaGetSymbolAddress((void**)&vl,  g_vl);
        cudaGetSymbolAddress((void**)&qph, g_qph); cudaGetSymbolAddress((void**)&qpl, g_qpl);
        cudaGetSymbolAddress((void**)&kph, g_kph); cudaGetSymbolAddress((void**)&kpl, g_kpl);
        cudaGetSymbolAddress((void**)&vph, g_vph); cudaGetSymbolAddress((void**)&vpl, g_vpl);
        cudaGetSymbolAddress((void**)&vth, g_vth); cudaGetSymbolAddress((void**)&vtl, g_vtl);
        cudaGetSymbolAddress((void**)&ch,  g_ch);  cudaGetSymbolAddress((void**)&cl,  g_cl);
        cudaGetSymbolAddress((void**)&wqh, g_wqh); cudaGetSymbolAddress((void**)&wql, g_wql);
        cudaGetSymbolAddress((void**)&wkh, g_wkh); cudaGetSymbolAddress((void**)&wkl, g_wkl);
        cudaGetSymbolAddress((void**)&wvh, g_wvh); cudaGetSymbolAddress((void**)&wvl, g_wvl);
        cudaGetSymbolAddress((void**)&woh, g_woh); cudaGetSymbolAddress((void**)&wol, g_wol);
    }

    const int n4 = MROWS * EMB / 4;
    const int sb = 256, sg = (n4 + sb - 1) / sb;
    split_bf16<<<sg, sb>>>(Q, qh, ql, n4);
    split_bf16<<<sg, sb>>>(K, kh, kl, n4);
    split_bf16<<<sg, sb>>>(V, vh, vl, n4);

    dim3 tb(32, 8), tg(EMB / 32, EMB / 32);
    transpose_split<<<tg, tb>>>(Wq, wqh, wql);
    transpose_split<<<tg, tb>>>(Wk, wkh, wkl);
    transpose_split<<<tg, tb>>>(Wv, wvh, wvl);
    transpose_split<<<tg, tb>>>(Wo, woh, wol);

    dim3 gg(EMB / 128, MROWS / 128);   // (8, 32)
    gemm_bf16x3<<<gg, 256>>>(qh, ql, wqh, wql, nullptr, qph, qpl, 0.125f, MROWS, EMB, EMB);
    gemm_bf16x3<<<gg, 256>>>(kh, kl, wkh, wkl, nullptr, kph, kpl, 1.0f,   MROWS, EMB, EMB);
    gemm_bf16x3<<<gg, 256>>>(vh, vl, wvh, wvl, nullptr, vph, vpl, 1.0f,   MROWS, EMB, EMB);

    dim3 vt(SEQ / 32, HD / 32, BATCH * NH);    // (64, 2, 32)
    transpose_v<<<vt, tb>>>(vph, vpl, vth, vtl);

    dim3 ga(SEQ / 64, NH, BATCH);              // (32, 16, 2)
    flash_mma<<<ga, 128>>>(qph, qpl, kph, kpl, vth, vtl, ch, cl);

    gemm_bf16x3<<<gg, 256>>>(ch, cl, woh, wol, out, nullptr, nullptr, 1.0f, MROWS, EMB, EMB);
}

// round 9
// speedup vs baseline: 1.0895x; 1.0895x over previous
#include <cuda_runtime.h>
#include <cuda_bf16.h>
#include <cstdint>

#define BATCH 2
#define SEQ   2048
#define EMB   1024
#define NH    16
#define HD    64
#define MROWS (BATCH*SEQ)   // 4096

// ---------------------------------------------------------------------------
// Scratch (static device globals — allocation guards forbid cudaMalloc)
// ---------------------------------------------------------------------------
__device__ __nv_bfloat16 g_qh[MROWS * EMB], g_ql[MROWS * EMB];
__device__ __nv_bfloat16 g_kh[MROWS * EMB], g_kl[MROWS * EMB];
__device__ __nv_bfloat16 g_vh[MROWS * EMB], g_vl[MROWS * EMB];
__device__ __nv_bfloat16 g_qph[MROWS * EMB], g_qpl[MROWS * EMB];
__device__ __nv_bfloat16 g_kph[MROWS * EMB], g_kpl[MROWS * EMB];
__device__ __nv_bfloat16 g_vph[MROWS * EMB], g_vpl[MROWS * EMB];
__device__ __nv_bfloat16 g_vth[MROWS * EMB], g_vtl[MROWS * EMB];
__device__ __nv_bfloat16 g_ch[MROWS * EMB], g_cl[MROWS * EMB];
__device__ __nv_bfloat16 g_wqh[EMB * EMB], g_wql[EMB * EMB];
__device__ __nv_bfloat16 g_wkh[EMB * EMB], g_wkl[EMB * EMB];
__device__ __nv_bfloat16 g_wvh[EMB * EMB], g_wvl[EMB * EMB];
__device__ __nv_bfloat16 g_woh[EMB * EMB], g_wol[EMB * EMB];

// ---------------------------------------------------------------------------
// Helpers
// ---------------------------------------------------------------------------
__device__ __forceinline__ uint32_t smem_u32(const void* p) {
    uint32_t a;
    asm("{ .reg .u64 t; cvta.to.shared.u64 t, %1; cvt.u32.u64 %0, t; }" : "=r"(a) : "l"(p));
    return a;
}

#define CP_ASYNC16(dst, src) \
    asm volatile("cp.async.cg.shared.global [%0], [%1], 16;" :: "r"((uint32_t)(dst)), "l"(src))
#define CP_COMMIT() asm volatile("cp.async.commit_group;" ::: "memory")
#define CP_WAIT0()  asm volatile("cp.async.wait_group 0;" ::: "memory")

__device__ __forceinline__ void mma16816(float* c, const uint32_t* a, const uint32_t* b) {
    asm volatile(
        "mma.sync.aligned.m16n8k16.row.col.f32.bf16.bf16.f32 "
        "{%0,%1,%2,%3}, {%4,%5,%6,%7}, {%8,%9}, {%0,%1,%2,%3};"
        : "+f"(c[0]), "+f"(c[1]), "+f"(c[2]), "+f"(c[3])
        : "r"(a[0]), "r"(a[1]), "r"(a[2]), "r"(a[3]), "r"(b[0]), "r"(b[1]));
}

__device__ __forceinline__ void split1(float x, __nv_bfloat16& h, __nv_bfloat16& l) {
    h = __float2bfloat16_rn(x);
    l = __float2bfloat16_rn(x - __bfloat162float(h));
}
__device__ __forceinline__ uint32_t pack2(__nv_bfloat16 a, __nv_bfloat16 b) {
    return (uint32_t)__bfloat16_as_ushort(a) | ((uint32_t)__bfloat16_as_ushort(b) << 16);
}
__device__ __forceinline__ void split_pack2(float x0, float x1, uint32_t& hi, uint32_t& lo) {
    __nv_bfloat16 h0, l0, h1, l1;
    split1(x0, h0, l0); split1(x1, h1, l1);
    hi = pack2(h0, h1); lo = pack2(l0, l1);
}

// ---------------------------------------------------------------------------
// Pre-pass 1: elementwise bf16 hi/lo split
// ---------------------------------------------------------------------------
__global__ void split_bf16(const float* __restrict__ x, __nv_bfloat16* __restrict__ hi,
                           __nv_bfloat16* __restrict__ lo, int n4) {
    int i = blockIdx.x * blockDim.x + threadIdx.x;
    if (i >= n4) return;
    float4 v = ((const float4*)x)[i];
    uint32_t h01, l01, h23, l23;
    split_pack2(v.x, v.y, h01, l01);
    split_pack2(v.z, v.w, h23, l23);
    ((uint2*)hi)[i] = make_uint2(h01, h23);
    ((uint2*)lo)[i] = make_uint2(l01, l23);
}

// ---------------------------------------------------------------------------
// Pre-pass 2: W[K][N] -> Wt hi/lo [N][K], bf16
// ---------------------------------------------------------------------------
__global__ void transpose_split(const float* __restrict__ W,
                                __nv_bfloat16* __restrict__ Thi,
                                __nv_bfloat16* __restrict__ Tlo) {
    __shared__ float t[32][33];
    int x = blockIdx.x * 32 + threadIdx.x;
    int y = blockIdx.y * 32 + threadIdx.y;
    #pragma unroll
    for (int i = 0; i < 32; i += 8)
        t[threadIdx.y + i][threadIdx.x] = W[(size_t)(y + i) * EMB + x];
    __syncthreads();
    int nx = blockIdx.y * 32 + threadIdx.x;
    int ny = blockIdx.x * 32 + threadIdx.y;
    #pragma unroll
    for (int i = 0; i < 32; i += 8) {
        float v = t[threadIdx.x][threadIdx.y + i];
        __nv_bfloat16 h, l;
        split1(v, h, l);
        Thi[(size_t)(ny + i) * EMB + nx] = h;
        Tlo[(size_t)(ny + i) * EMB + nx] = l;
    }
}

// ---------------------------------------------------------------------------
// V transpose: [b*S+s][h*64+d] -> [(b*16+h)*64+d][s]
// ---------------------------------------------------------------------------
__global__ void transpose_v(const __nv_bfloat16* __restrict__ vh,
                            const __nv_bfloat16* __restrict__ vl,
                            __nv_bfloat16* __restrict__ th,
                            __nv_bfloat16* __restrict__ tl) {
    __shared__ __nv_bfloat16 a[32][33], c[32][33];
    const int bh = blockIdx.z;
    const int b = bh >> 4, h = bh & 15;
    const int s0 = blockIdx.x * 32, d0 = blockIdx.y * 32;
    const int tx = threadIdx.x, ty = threadIdx.y;
    #pragma unroll
    for (int i = 0; i < 32; i += 8) {
        size_t src = (size_t)(b * SEQ + s0 + ty + i) * EMB + h * HD + d0 + tx;
        a[ty + i][tx] = vh[src];
        c[ty + i][tx] = vl[src];
    }
    __syncthreads();
    #pragma unroll
    for (int i = 0; i < 32; i += 8) {
        size_t dst = (size_t)(bh * HD + d0 + ty + i) * SEQ + s0 + tx;
        th[dst] = a[tx][ty + i];
        tl[dst] = c[tx][ty + i];
    }
}

// ---------------------------------------------------------------------------
// mma.sync 3x-bf16 GEMM (round-7 proven config): block 128x128, BK=32,
// 256 threads (8 warps 2x4, warp tile 64x32), single-stage cp.async.
// SMEM: 4 tiles x 128 rows x 20 words = 40960 B static.
// ---------------------------------------------------------------------------
#define TW 20
#define TILE_W (128 * TW)

__global__ __launch_bounds__(256) void gemm_bf16x3(
    const __nv_bfloat16* __restrict__ Ahi, const __nv_bfloat16* __restrict__ Alo,
    const __nv_bfloat16* __restrict__ Bhi, const __nv_bfloat16* __restrict__ Blo,
    float* __restrict__ Cf, __nv_bfloat16* __restrict__ Chi,
    __nv_bfloat16* __restrict__ Clo, float scale, int M, int N, int K)
{
    __shared__ uint32_t sm[4 * TILE_W];
    const int tid = threadIdx.x;
    const int wid = tid >> 5, lane = tid & 31;
    const int g = lane >> 2, t = lane & 3;
    const int wm = wid & 1, wn = wid >> 1;
    const int bm = blockIdx.y * 128, bn = blockIdx.x * 128;

    const uint32_t sbase = smem_u32(sm);
    const int r0 = tid >> 2, c0 = tid & 3;
    const __nv_bfloat16* gsrc[4] = {
        Ahi + (size_t)bm * K, Alo + (size_t)bm * K,
        Bhi + (size_t)bn * K, Blo + (size_t)bn * K
    };

    float acc[4][4][4] = {};

    const int NS = K / 32;
    for (int s = 0; s < NS; s++) {
        const int k0 = s * 32;
        #pragma unroll
        for (int tile = 0; tile < 4; tile++) {
            const __nv_bfloat16* src = gsrc[tile] + (size_t)r0 * K + k0 + c0 * 8;
            uint32_t d = sbase + (tile * TILE_W + r0 * TW + c0 * 4) * 4;
            CP_ASYNC16(d, src);
            CP_ASYNC16(d + 64 * TW * 4, src + (size_t)64 * K);
        }
        CP_COMMIT();
        CP_WAIT0();
        __syncthreads();

        const uint32_t* As  = sm + 0 * TILE_W;
        const uint32_t* Als = sm + 1 * TILE_W;
        const uint32_t* Bs  = sm + 2 * TILE_W;
        const uint32_t* Bls = sm + 3 * TILE_W;

        #pragma unroll
        for (int kk = 0; kk < 2; kk++) {
            const int kw = kk * 8;
            uint32_t ah[4][4], al[4][4], bh[4][2], bl[4][2];
            #pragma unroll
            for (int mf = 0; mf < 4; mf++) {
                const int m0 = wm * 64 + mf * 16;
                const int i0 = (m0 + g) * TW + t + kw;
                const int i8 = (m0 + g + 8) * TW + t + kw;
                ah[mf][0] = As[i0];  ah[mf][1] = As[i8];
                ah[mf][2] = As[i0 + 4]; ah[mf][3] = As[i8 + 4];
                al[mf][0] = Als[i0]; al[mf][1] = Als[i8];
                al[mf][2] = Als[i0 + 4]; al[mf][3] = Als[i8 + 4];
            }
            #pragma unroll
            for (int nf = 0; nf < 4; nf++) {
                const int n0 = wn * 32 + nf * 8;
                const int j0 = (n0 + g) * TW + t + kw;
                bh[nf][0] = Bs[j0];  bh[nf][1] = Bs[j0 + 4];
                bl[nf][0] = Bls[j0]; bl[nf][1] = Bls[j0 + 4];
            }
            #pragma unroll
            for (int mf = 0; mf < 4; mf++)
                #pragma unroll
                for (int nf = 0; nf < 4; nf++) {
                    mma16816(acc[mf][nf], ah[mf], bh[nf]);
                    mma16816(acc[mf][nf], ah[mf], bl[nf]);
                    mma16816(acc[mf][nf], al[mf], bh[nf]);
                }
        }
        __syncthreads();
    }

    #pragma unroll
    for (int mf = 0; mf < 4; mf++) {
        const int m = bm + wm * 64 + mf * 16 + g;
        #pragma unroll
        for (int nf = 0; nf < 4; nf++) {
            const int n = bn + wn * 32 + nf * 8 + 2 * t;
            float v0 = acc[mf][nf][0], v1 = acc[mf][nf][1];
            float v2 = acc[mf][nf][2], v3 = acc[mf][nf][3];
            if (Cf) {
                *(float2*)(Cf + (size_t)m * N + n)       = make_float2(v0, v1);
                *(float2*)(Cf + (size_t)(m + 8) * N + n) = make_float2(v2, v3);
            }
            if (Chi) {
                uint32_t h01, l01, h23, l23;
                split_pack2(v0 * scale, v1 * scale, h01, l01);
                split_pack2(v2 * scale, v3 * scale, h23, l23);
                *(uint32_t*)(Chi + (size_t)m * N + n)       = h01;
                *(uint32_t*)(Clo + (size_t)m * N + n)       = l01;
                *(uint32_t*)(Chi + (size_t)(m + 8) * N + n) = h23;
                *(uint32_t*)(Clo + (size_t)(m + 8) * N + n) = l23;
            }
        }
    }
}

// ---------------------------------------------------------------------------
// Flash attention on mma.sync — WIDENED: 128 queries/block, 8 warps (256 thr).
// KV tile = 32, single-buffered (round-7 proven). SMEM 19456 B static.
// Halves block count (512) -> halves K/V L2 streaming traffic per query.
// ---------------------------------------------------------------------------
#define FKP 72
#define FVP 40

__global__ __launch_bounds__(256) void flash_mma(
    const __nv_bfloat16* __restrict__ Qh, const __nv_bfloat16* __restrict__ Ql,
    const __nv_bfloat16* __restrict__ Kh, const __nv_bfloat16* __restrict__ Kl,
    const __nv_bfloat16* __restrict__ Vth, const __nv_bfloat16* __restrict__ Vtl,
    __nv_bfloat16* __restrict__ Ch, __nv_bfloat16* __restrict__ Cl)
{
    __shared__ __nv_bfloat16 Ksh[32 * FKP], Ksl[32 * FKP];
    __shared__ __nv_bfloat16 Vsh[64 * FVP], Vsl[64 * FVP];

    const int tid = threadIdx.x, wid = tid >> 5, lane = tid & 31;
    const int g = lane >> 2, t = lane & 3;
    const int qt = blockIdx.x, h = blockIdx.y, b = blockIdx.z;
    const int q0 = qt * 128, m0 = wid * 16;    // 8 warps x 16 rows = 128 queries

    // Q fragments from global (pre-scaled by 1/8)
    uint32_t qhf[4][4], qlf[4][4];
    {
        const size_t rbase = (size_t)(b * SEQ + q0 + m0 + g) * EMB + h * HD;
        const __nv_bfloat16* q0h = Qh + rbase;
        const __nv_bfloat16* q8h = q0h + (size_t)8 * EMB;
        const __nv_bfloat16* q0l = Ql + rbase;
        const __nv_bfloat16* q8l = q0l + (size_t)8 * EMB;
        #pragma unroll
        for (int kc = 0; kc < 4; kc++) {
            const int d0 = kc * 16 + 2 * t;
            qhf[kc][0] = *(const uint32_t*)(q0h + d0);
            qhf[kc][1] = *(const uint32_t*)(q8h + d0);
            qhf[kc][2] = *(const uint32_t*)(q0h + d0 + 8);
            qhf[kc][3] = *(const uint32_t*)(q8h + d0 + 8);
            qlf[kc][0] = *(const uint32_t*)(q0l + d0);
            qlf[kc][1] = *(const uint32_t*)(q8l + d0);
            qlf[kc][2] = *(const uint32_t*)(q0l + d0 + 8);
            qlf[kc][3] = *(const uint32_t*)(q8l + d0 + 8);
        }
    }

    float O[8][4] = {};
    float m_g = -1e30f, m_g8 = -1e30f, l_g = 0.f, l_g8 = 0.f;

    // loaders: 256 threads, 1 chunk each.
    // K: 32 rows x 8 chunks of 16B (hi and lo). V: 64 rows x 4 chunks.
    const int kr = tid >> 3, kc8 = tid & 7;
    const int vd = tid >> 2, vc = tid & 3;
    const __nv_bfloat16* khb = Kh + (size_t)(b * SEQ) * EMB + h * HD;
    const __nv_bfloat16* klb = Kl + (size_t)(b * SEQ) * EMB + h * HD;
    const __nv_bfloat16* vhb = Vth + (size_t)((b * NH + h) * HD) * SEQ;
    const __nv_bfloat16* vlb = Vtl + (size_t)((b * NH + h) * HD) * SEQ;
    const uint32_t sKh = smem_u32(Ksh), sKl = smem_u32(Ksl);
    const uint32_t sVh = smem_u32(Vsh), sVl = smem_u32(Vsl);

    for (int j0 = 0; j0 < SEQ; j0 += 32) {
        // stage K/V tiles
        {
            const __nv_bfloat16* ks = khb + (size_t)(j0 + kr) * EMB + kc8 * 8;
            const __nv_bfloat16* ls = klb + (size_t)(j0 + kr) * EMB + kc8 * 8;
            const uint32_t kd = kr * (FKP * 2) + kc8 * 16;
            CP_ASYNC16(sKh + kd, ks);
            CP_ASYNC16(sKl + kd, ls);
            const __nv_bfloat16* vs = vhb + (size_t)vd * SEQ + j0 + vc * 8;
            const __nv_bfloat16* ws = vlb + (size_t)vd * SEQ + j0 + vc * 8;
            const uint32_t vdd = vd * (FVP * 2) + vc * 16;
            CP_ASYNC16(sVh + vdd, vs);
            CP_ASYNC16(sVl + vdd, ws);
        }
        CP_COMMIT();
        CP_WAIT0();
        __syncthreads();

        // S = Q K^T  (16x32 per warp)
        float s[4][4] = {};
        #pragma unroll
        for (int kc = 0; kc < 4; kc++) {
            uint32_t bh_[4][2], bl_[4][2];
            #pragma unroll
            for (int nf = 0; nf < 4; nf++) {
                const int base = (nf * 8 + g) * FKP + kc * 16 + 2 * t;
                bh_[nf][0] = *(const uint32_t*)(Ksh + base);
                bh_[nf][1] = *(const uint32_t*)(Ksh + base + 8);
                bl_[nf][0] = *(const uint32_t*)(Ksl + base);
                bl_[nf][1] = *(const uint32_t*)(Ksl + base + 8);
            }
            #pragma unroll
            for (int nf = 0; nf < 4; nf++) {
                mma16816(s[nf], qhf[kc], bh_[nf]);
                mma16816(s[nf], qhf[kc], bl_[nf]);
                mma16816(s[nf], qlf[kc], bh_[nf]);
            }
        }

        // online softmax (rows g and g+8)
        float mx0 = -1e30f, mx8 = -1e30f;
        #pragma unroll
        for (int nf = 0; nf < 4; nf++) {
            mx0 = fmaxf(mx0, fmaxf(s[nf][0], s[nf][1]));
            mx8 = fmaxf(mx8, fmaxf(s[nf][2], s[nf][3]));
        }
        mx0 = fmaxf(mx0, __shfl_xor_sync(0xffffffffu, mx0, 1));
        mx0 = fmaxf(mx0, __shfl_xor_sync(0xffffffffu, mx0, 2));
        mx8 = fmaxf(mx8, __shfl_xor_sync(0xffffffffu, mx8, 1));
        mx8 = fmaxf(mx8, __shfl_xor_sync(0xffffffffu, mx8, 2));
        const float mn_g = fmaxf(m_g, mx0), mn_g8 = fmaxf(m_g8, mx8);
        const float alpha_g = __expf(m_g - mn_g), alpha_g8 = __expf(m_g8 - mn_g8);
        m_g = mn_g; m_g8 = mn_g8;

        float p[4][4];
        float sum0 = 0.f, sum8 = 0.f;
        #pragma unroll
        for (int nf = 0; nf < 4; nf++) {
            p[nf][0] = __expf(s[nf][0] - mn_g);
            p[nf][1] = __expf(s[nf][1] - mn_g);
            p[nf][2] = __expf(s[nf][2] - mn_g8);
            p[nf][3] = __expf(s[nf][3] - mn_g8);
            sum0 += p[nf][0] + p[nf][1];
            sum8 += p[nf][2] + p[nf][3];
        }
        sum0 += __shfl_xor_sync(0xffffffffu, sum0, 1);
        sum0 += __shfl_xor_sync(0xffffffffu, sum0, 2);
        sum8 += __shfl_xor_sync(0xffffffffu, sum8, 1);
        sum8 += __shfl_xor_sync(0xffffffffu, sum8, 2);
        l_g  = l_g  * alpha_g  + sum0;
        l_g8 = l_g8 * alpha_g8 + sum8;

        #pragma unroll
        for (int nf2 = 0; nf2 < 8; nf2++) {
            O[nf2][0] *= alpha_g;  O[nf2][1] *= alpha_g;
            O[nf2][2] *= alpha_g8; O[nf2][3] *= alpha_g8;
        }

        // P fragments (S C-frag == PV A-frag layout)
        uint32_t pah[2][4], pal[2][4];
        #pragma unroll
        for (int kc2 = 0; kc2 < 2; kc2++) {
            const int nA = 2 * kc2, nB = 2 * kc2 + 1;
            split_pack2(p[nA][0], p[nA][1], pah[kc2][0], pal[kc2][0]);
            split_pack2(p[nA][2], p[nA][3], pah[kc2][1], pal[kc2][1]);
            split_pack2(p[nB][0], p[nB][1], pah[kc2][2], pal[kc2][2]);
            split_pack2(p[nB][2], p[nB][3], pah[kc2][3], pal[kc2][3]);
        }

        // O += P V
        #pragma unroll
        for (int nf2 = 0; nf2 < 8; nf2++) {
            #pragma unroll
            for (int kc2 = 0; kc2 < 2; kc2++) {
                const int base = (nf2 * 8 + g) * FVP + kc2 * 16 + 2 * t;
                uint32_t vbh[2], vbl[2];
                vbh[0] = *(const uint32_t*)(Vsh + base);
                vbh[1] = *(const uint32_t*)(Vsh + base + 8);
                vbl[0] = *(const uint32_t*)(Vsl + base);
                vbl[1] = *(const uint32_t*)(Vsl + base + 8);
                mma16816(O[nf2], pah[kc2], vbh);
                mma16816(O[nf2], pal[kc2], vbh);
                mma16816(O[nf2], pah[kc2], vbl);
            }
        }
        __syncthreads();   // all reads done before next tile overwrite
    }

    // epilogue: normalize, split to bf16 hi/lo
    const float li_g = 1.0f / l_g, li_g8 = 1.0f / l_g8;
    const size_t row0 = (size_t)(b * SEQ + q0 + m0 + g) * EMB;
    const size_t row8 = row0 + (size_t)8 * EMB;
    #pragma unroll
    for (int nf2 = 0; nf2 < 8; nf2++) {
        const int col = h * HD + nf2 * 8 + 2 * t;
        uint32_t h01, l01, h23, l23;
        split_pack2(O[nf2][0] * li_g,  O[nf2][1] * li_g,  h01, l01);
        split_pack2(O[nf2][2] * li_g8, O[nf2][3] * li_g8, h23, l23);
        *(uint32_t*)(Ch + row0 + col) = h01;
        *(uint32_t*)(Cl + row0 + col) = l01;
        *(uint32_t*)(Ch + row8 + col) = h23;
        *(uint32_t*)(Cl + row8 + col) = l23;
    }
}

// ---------------------------------------------------------------------------
extern "C" void kernel_launch(void* const* d_in, const int* in_sizes, int n_in,
                              void* d_out, int out_size)
{
    const float* Q  = (const float*)d_in[0];
    const float* K  = (const float*)d_in[1];
    const float* V  = (const float*)d_in[2];
    const float* Wq = (const float*)d_in[3];
    const float* Wk = (const float*)d_in[4];
    const float* Wv = (const float*)d_in[5];
    const float* Wo = (const float*)d_in[6];
    float* out = (float*)d_out;

    static __nv_bfloat16 *qh, *ql, *kh, *kl, *vh, *vl;
    static __nv_bfloat16 *qph, *qpl, *kph, *kpl, *vph, *vpl, *vth, *vtl, *ch, *cl;
    static __nv_bfloat16 *wqh, *wql, *wkh, *wkl, *wvh, *wvl, *woh, *wol;
    static bool inited = false;
    if (!inited) {
        inited = true;
        cudaGetSymbolAddress((void**)&qh,  g_qh);  cudaGetSymbolAddress((void**)&ql,  g_ql);
        cudaGetSymbolAddress((void**)&kh,  g_kh);  cudaGetSymbolAddress((void**)&kl,  g_kl);
        cudaGetSymbolAddress((void**)&vh,  g_vh);  cudaGetSymbolAddress((void**)&vl,  g_vl);
        cudaGetSymbolAddress((void**)&qph, g_qph); cudaGetSymbolAddress((void**)&qpl, g_qpl);
        cudaGetSymbolAddress((void**)&kph, g_kph); cudaGetSymbolAddress((void**)&kpl, g_kpl);
        cudaGetSymbolAddress((void**)&vph, g_vph); cudaGetSymbolAddress((void**)&vpl, g_vpl);
        cudaGetSymbolAddress((void**)&vth, g_vth); cudaGetSymbolAddress((void**)&vtl, g_vtl);
        cudaGetSymbolAddress((void**)&ch,  g_ch);  cudaGetSymbolAddress((void**)&cl,  g_cl);
        cudaGetSymbolAddress((void**)&wqh, g_wqh); cudaGetSymbolAddress((void**)&wql, g_wql);
        cudaGetSymbolAddress((void**)&wkh, g_wkh); cudaGetSymbolAddress((void**)&wkl, g_wkl);
        cudaGetSymbolAddress((void**)&wvh, g_wvh); cudaGetSymbolAddress((void**)&wvl, g_wvl);
        cudaGetSymbolAddress((void**)&woh, g_woh); cudaGetSymbolAddress((void**)&wol, g_wol);
    }

    const int n4 = MROWS * EMB / 4;
    const int sb = 256, sg = (n4 + sb - 1) / sb;
    split_bf16<<<sg, sb>>>(Q, qh, ql, n4);
    split_bf16<<<sg, sb>>>(K, kh, kl, n4);
    split_bf16<<<sg, sb>>>(V, vh, vl, n4);

    dim3 tb(32, 8), tg(EMB / 32, EMB / 32);
    transpose_split<<<tg, tb>>>(Wq, wqh, wql);
    transpose_split<<<tg, tb>>>(Wk, wkh, wkl);
    transpose_split<<<tg, tb>>>(Wv, wvh, wvl);
    transpose_split<<<tg, tb>>>(Wo, woh, wol);

    dim3 gg(EMB / 128, MROWS / 128);   // (8, 32)
    gemm_bf16x3<<<gg, 256>>>(qh, ql, wqh, wql, nullptr, qph, qpl, 0.125f, MROWS, EMB, EMB);
    gemm_bf16x3<<<gg, 256>>>(kh, kl, wkh, wkl, nullptr, kph, kpl, 1.0f,   MROWS, EMB, EMB);
    gemm_bf16x3<<<gg, 256>>>(vh, vl, wvh, wvl, nullptr, vph, vpl, 1.0f,   MROWS, EMB, EMB);

    dim3 vt(SEQ / 32, HD / 32, BATCH * NH);    // (64, 2, 32)
    transpose_v<<<vt, tb>>>(vph, vpl, vth, vtl);

    dim3 ga(SEQ / 128, NH, BATCH);             // (16, 16, 2)
    flash_mma<<<ga, 256>>>(qph, qpl, kph, kpl, vth, vtl, ch, cl);

    gemm_bf16x3<<<gg, 256>>>(ch, cl, woh, wol, out, nullptr, nullptr, 1.0f, MROWS, EMB, EMB);
}

// round 11
// speedup vs baseline: 1.1164x; 1.0248x over previous
#include <cuda_runtime.h>
#include <cuda_bf16.h>
#include <cstdint>

#define BATCH 2
#define SEQ   2048
#define EMB   1024
#define NH    16
#define HD    64
#define MROWS (BATCH*SEQ)   // 4096

// ---------------------------------------------------------------------------
// Scratch (static device globals — allocation guards forbid cudaMalloc).
// All kernels reference these symbols DIRECTLY (no runtime pointer passing).
// ---------------------------------------------------------------------------
__device__ __nv_bfloat16 g_qh[MROWS * EMB], g_ql[MROWS * EMB];
__device__ __nv_bfloat16 g_kh[MROWS * EMB], g_kl[MROWS * EMB];
__device__ __nv_bfloat16 g_vh[MROWS * EMB], g_vl[MROWS * EMB];
__device__ __nv_bfloat16 g_qph[MROWS * EMB], g_qpl[MROWS * EMB];
__device__ __nv_bfloat16 g_kph[MROWS * EMB], g_kpl[MROWS * EMB];
__device__ __nv_bfloat16 g_vph[MROWS * EMB], g_vpl[MROWS * EMB];
__device__ __nv_bfloat16 g_vth[MROWS * EMB], g_vtl[MROWS * EMB];
__device__ __nv_bfloat16 g_ch[MROWS * EMB], g_cl[MROWS * EMB];
__device__ __nv_bfloat16 g_wqh[EMB * EMB], g_wql[EMB * EMB];
__device__ __nv_bfloat16 g_wkh[EMB * EMB], g_wkl[EMB * EMB];
__device__ __nv_bfloat16 g_wvh[EMB * EMB], g_wvl[EMB * EMB];
__device__ __nv_bfloat16 g_woh[EMB * EMB], g_wol[EMB * EMB];

// ---------------------------------------------------------------------------
// Helpers
// ---------------------------------------------------------------------------
__device__ __forceinline__ uint32_t smem_u32(const void* p) {
    uint32_t a;
    asm("{ .reg .u64 t; cvta.to.shared.u64 t, %1; cvt.u32.u64 %0, t; }" : "=r"(a) : "l"(p));
    return a;
}

#define CP_ASYNC16(dst, src) \
    asm volatile("cp.async.cg.shared.global [%0], [%1], 16;" :: "r"((uint32_t)(dst)), "l"(src))
#define CP_COMMIT() asm volatile("cp.async.commit_group;" ::: "memory")
#define CP_WAIT0()  asm volatile("cp.async.wait_group 0;" ::: "memory")

__device__ __forceinline__ void mma16816(float* c, const uint32_t* a, const uint32_t* b) {
    asm volatile(
        "mma.sync.aligned.m16n8k16.row.col.f32.bf16.bf16.f32 "
        "{%0,%1,%2,%3}, {%4,%5,%6,%7}, {%8,%9}, {%0,%1,%2,%3};"
        : "+f"(c[0]), "+f"(c[1]), "+f"(c[2]), "+f"(c[3])
        : "r"(a[0]), "r"(a[1]), "r"(a[2]), "r"(a[3]), "r"(b[0]), "r"(b[1]));
}

__device__ __forceinline__ void split1(float x, __nv_bfloat16& h, __nv_bfloat16& l) {
    h = __float2bfloat16_rn(x);
    l = __float2bfloat16_rn(x - __bfloat162float(h));
}
__device__ __forceinline__ uint32_t pack2(__nv_bfloat16 a, __nv_bfloat16 b) {
    return (uint32_t)__bfloat16_as_ushort(a) | ((uint32_t)__bfloat16_as_ushort(b) << 16);
}
__device__ __forceinline__ void split_pack2(float x0, float x1, uint32_t& hi, uint32_t& lo) {
    __nv_bfloat16 h0, l0, h1, l1;
    split1(x0, h0, l0); split1(x1, h1, l1);
    hi = pack2(h0, h1); lo = pack2(l0, l1);
}

// ---------------------------------------------------------------------------
// Pre-pass 1: batched bf16 hi/lo split of Q,K,V (grid.y in {0,1,2})
// ---------------------------------------------------------------------------
__global__ void split_bf16_3(const float* __restrict__ Q, const float* __restrict__ K,
                             const float* __restrict__ V, int n4) {
    const int z = blockIdx.y;
    int i = blockIdx.x * blockDim.x + threadIdx.x;
    if (i >= n4) return;
    const float* x;
    __nv_bfloat16 *hi, *lo;
    switch (z) {
        case 0:  x = Q; hi = g_qh; lo = g_ql; break;
        case 1:  x = K; hi = g_kh; lo = g_kl; break;
        default: x = V; hi = g_vh; lo = g_vl; break;
    }
    float4 v = ((const float4*)x)[i];
    uint32_t h01, l01, h23, l23;
    split_pack2(v.x, v.y, h01, l01);
    split_pack2(v.z, v.w, h23, l23);
    ((uint2*)hi)[i] = make_uint2(h01, h23);
    ((uint2*)lo)[i] = make_uint2(l01, l23);
}

// ---------------------------------------------------------------------------
// Pre-pass 2: batched W[K][N] -> Wt hi/lo [N][K] (grid.z in {0..3})
// ---------------------------------------------------------------------------
__global__ void transpose_split_4(const float* __restrict__ Wq, const float* __restrict__ Wk,
                                  const float* __restrict__ Wv, const float* __restrict__ Wo) {
    __shared__ float t[32][33];
    const float* W;
    __nv_bfloat16 *Thi, *Tlo;
    switch (blockIdx.z) {
        case 0:  W = Wq; Thi = g_wqh; Tlo = g_wql; break;
        case 1:  W = Wk; Thi = g_wkh; Tlo = g_wkl; break;
        case 2:  W = Wv; Thi = g_wvh; Tlo = g_wvl; break;
        default: W = Wo; Thi = g_woh; Tlo = g_wol; break;
    }
    int x = blockIdx.x * 32 + threadIdx.x;
    int y = blockIdx.y * 32 + threadIdx.y;
    #pragma unroll
    for (int i = 0; i < 32; i += 8)
        t[threadIdx.y + i][threadIdx.x] = W[(size_t)(y + i) * EMB + x];
    __syncthreads();
    int nx = blockIdx.y * 32 + threadIdx.x;
    int ny = blockIdx.x * 32 + threadIdx.y;
    #pragma unroll
    for (int i = 0; i < 32; i += 8) {
        float v = t[threadIdx.x][threadIdx.y + i];
        __nv_bfloat16 h, l;
        split1(v, h, l);
        Thi[(size_t)(ny + i) * EMB + nx] = h;
        Tlo[(size_t)(ny + i) * EMB + nx] = l;
    }
}

// ---------------------------------------------------------------------------
// V transpose: [b*S+s][h*64+d] -> [(b*16+h)*64+d][s]
// ---------------------------------------------------------------------------
__global__ void transpose_v() {
    __shared__ __nv_bfloat16 a[32][33], c[32][33];
    const int bh = blockIdx.z;
    const int b = bh >> 4, h = bh & 15;
    const int s0 = blockIdx.x * 32, d0 = blockIdx.y * 32;
    const int tx = threadIdx.x, ty = threadIdx.y;
    #pragma unroll
    for (int i = 0; i < 32; i += 8) {
        size_t src = (size_t)(b * SEQ + s0 + ty + i) * EMB + h * HD + d0 + tx;
        a[ty + i][tx] = g_vph[src];
        c[ty + i][tx] = g_vpl[src];
    }
    __syncthreads();
    #pragma unroll
    for (int i = 0; i < 32; i += 8) {
        size_t dst = (size_t)(bh * HD + d0 + ty + i) * SEQ + s0 + tx;
        g_vth[dst] = a[tx][ty + i];
        g_vtl[dst] = c[tx][ty + i];
    }
}

// ---------------------------------------------------------------------------
// mma.sync 3x-bf16 GEMM core (round-7 proven): block 128x128, BK=32,
// 256 threads (8 warps 2x4, warp tile 64x32), single-stage cp.async.
// SMEM: 4 tiles x 128 rows x 20 words = 40960 B static (in caller).
// ---------------------------------------------------------------------------
#define TW 20
#define TILE_W (128 * TW)

__device__ __forceinline__ void gemm_core(
    const __nv_bfloat16* __restrict__ Ahi, const __nv_bfloat16* __restrict__ Alo,
    const __nv_bfloat16* __restrict__ Bhi, const __nv_bfloat16* __restrict__ Blo,
    float* __restrict__ Cf, __nv_bfloat16* __restrict__ Chi,
    __nv_bfloat16* __restrict__ Clo, float scale, int M, int N, int K,
    uint32_t* sm)
{
    const int tid = threadIdx.x;
    const int wid = tid >> 5, lane = tid & 31;
    const int g = lane >> 2, t = lane & 3;
    const int wm = wid & 1, wn = wid >> 1;
    const int bm = blockIdx.y * 128, bn = blockIdx.x * 128;

    const uint32_t sbase = smem_u32(sm);
    const int r0 = tid >> 2, c0 = tid & 3;
    const __nv_bfloat16* gsrc[4] = {
        Ahi + (size_t)bm * K, Alo + (size_t)bm * K,
        Bhi + (size_t)bn * K, Blo + (size_t)bn * K
    };

    float acc[4][4][4] = {};

    const int NS = K / 32;
    for (int s = 0; s < NS; s++) {
        const int k0 = s * 32;
        #pragma unroll
        for (int tile = 0; tile < 4; tile++) {
            const __nv_bfloat16* src = gsrc[tile] + (size_t)r0 * K + k0 + c0 * 8;
            uint32_t d = sbase + (tile * TILE_W + r0 * TW + c0 * 4) * 4;
            CP_ASYNC16(d, src);
            CP_ASYNC16(d + 64 * TW * 4, src + (size_t)64 * K);
        }
        CP_COMMIT();
        CP_WAIT0();
        __syncthreads();

        const uint32_t* As  = sm + 0 * TILE_W;
        const uint32_t* Als = sm + 1 * TILE_W;
        const uint32_t* Bs  = sm + 2 * TILE_W;
        const uint32_t* Bls = sm + 3 * TILE_W;

        #pragma unroll
        for (int kk = 0; kk < 2; kk++) {
            const int kw = kk * 8;
            uint32_t ah[4][4], al[4][4], bh[4][2], bl[4][2];
            #pragma unroll
            for (int mf = 0; mf < 4; mf++) {
                const int m0 = wm * 64 + mf * 16;
                const int i0 = (m0 + g) * TW + t + kw;
                const int i8 = (m0 + g + 8) * TW + t + kw;
                ah[mf][0] = As[i0];  ah[mf][1] = As[i8];
                ah[mf][2] = As[i0 + 4]; ah[mf][3] = As[i8 + 4];
                al[mf][0] = Als[i0]; al[mf][1] = Als[i8];
                al[mf][2] = Als[i0 + 4]; al[mf][3] = Als[i8 + 4];
            }
            #pragma unroll
            for (int nf = 0; nf < 4; nf++) {
                const int n0 = wn * 32 + nf * 8;
                const int j0 = (n0 + g) * TW + t + kw;
                bh[nf][0] = Bs[j0];  bh[nf][1] = Bs[j0 + 4];
                bl[nf][0] = Bls[j0]; bl[nf][1] = Bls[j0 + 4];
            }
            #pragma unroll
            for (int mf = 0; mf < 4; mf++)
                #pragma unroll
                for (int nf = 0; nf < 4; nf++) {
                    mma16816(acc[mf][nf], ah[mf], bh[nf]);
                    mma16816(acc[mf][nf], ah[mf], bl[nf]);
                    mma16816(acc[mf][nf], al[mf], bh[nf]);
                }
        }
        __syncthreads();
    }

    #pragma unroll
    for (int mf = 0; mf < 4; mf++) {
        const int m = bm + wm * 64 + mf * 16 + g;
        #pragma unroll
        for (int nf = 0; nf < 4; nf++) {
            const int n = bn + wn * 32 + nf * 8 + 2 * t;
            float v0 = acc[mf][nf][0], v1 = acc[mf][nf][1];
            float v2 = acc[mf][nf][2], v3 = acc[mf][nf][3];
            if (Cf) {
                *(float2*)(Cf + (size_t)m * N + n)       = make_float2(v0, v1);
                *(float2*)(Cf + (size_t)(m + 8) * N + n) = make_float2(v2, v3);
            }
            if (Chi) {
                uint32_t h01, l01, h23, l23;
                split_pack2(v0 * scale, v1 * scale, h01, l01);
                split_pack2(v2 * scale, v3 * scale, h23, l23);
                *(uint32_t*)(Chi + (size_t)m * N + n)       = h01;
                *(uint32_t*)(Clo + (size_t)m * N + n)       = l01;
                *(uint32_t*)(Chi + (size_t)(m + 8) * N + n) = h23;
                *(uint32_t*)(Clo + (size_t)(m + 8) * N + n) = l23;
            }
        }
    }
}

// Batched Q/K/V projection GEMM: grid.z selects tensor set via global symbols.
// 768 blocks in one launch -> waves overlap, one tail instead of three.
__global__ __launch_bounds__(256) void gemm_qkv(int M, int N, int K) {
    __shared__ uint32_t sm[4 * TILE_W];
    const __nv_bfloat16 *Ahi, *Alo, *Bhi, *Blo;
    __nv_bfloat16 *Chi, *Clo;
    float scale;
    switch (blockIdx.z) {
        case 0:  Ahi = g_qh; Alo = g_ql; Bhi = g_wqh; Blo = g_wql;
                 Chi = g_qph; Clo = g_qpl; scale = 0.125f; break;
        case 1:  Ahi = g_kh; Alo = g_kl; Bhi = g_wkh; Blo = g_wkl;
                 Chi = g_kph; Clo = g_kpl; scale = 1.0f; break;
        default: Ahi = g_vh; Alo = g_vl; Bhi = g_wvh; Blo = g_wvl;
                 Chi = g_vph; Clo = g_vpl; scale = 1.0f; break;
    }
    gemm_core(Ahi, Alo, Bhi, Blo, nullptr, Chi, Clo, scale, M, N, K, sm);
}

__global__ __launch_bounds__(256) void gemm_wo(float* __restrict__ Cf,
                                               int M, int N, int K) {
    __shared__ uint32_t sm[4 * TILE_W];
    gemm_core(g_ch, g_cl, g_woh, g_wol, Cf, nullptr, nullptr, 1.0f, M, N, K, sm);
}

// ---------------------------------------------------------------------------
// Flash attention on mma.sync (round-9 proven): 128 queries/block, 8 warps,
// KV tile = 32, single-buffered. SMEM 19456 B static. All I/O via globals.
// ---------------------------------------------------------------------------
#define FKP 72
#define FVP 40

__global__ __launch_bounds__(256) void flash_mma() {
    __shared__ __nv_bfloat16 Ksh[32 * FKP], Ksl[32 * FKP];
    __shared__ __nv_bfloat16 Vsh[64 * FVP], Vsl[64 * FVP];

    const int tid = threadIdx.x, wid = tid >> 5, lane = tid & 31;
    const int g = lane >> 2, t = lane & 3;
    const int qt = blockIdx.x, h = blockIdx.y, b = blockIdx.z;
    const int q0 = qt * 128, m0 = wid * 16;

    uint32_t qhf[4][4], qlf[4][4];
    {
        const size_t rbase = (size_t)(b * SEQ + q0 + m0 + g) * EMB + h * HD;
        const __nv_bfloat16* q0h = g_qph + rbase;
        const __nv_bfloat16* q8h = q0h + (size_t)8 * EMB;
        const __nv_bfloat16* q0l = g_qpl + rbase;
        const __nv_bfloat16* q8l = q0l + (size_t)8 * EMB;
        #pragma unroll
        for (int kc = 0; kc < 4; kc++) {
            const int d0 = kc * 16 + 2 * t;
            qhf[kc][0] = *(const uint32_t*)(q0h + d0);
            qhf[kc][1] = *(const uint32_t*)(q8h + d0);
            qhf[kc][2] = *(const uint32_t*)(q0h + d0 + 8);
            qhf[kc][3] = *(const uint32_t*)(q8h + d0 + 8);
            qlf[kc][0] = *(const uint32_t*)(q0l + d0);
            qlf[kc][1] = *(const uint32_t*)(q8l + d0);
            qlf[kc][2] = *(const uint32_t*)(q0l + d0 + 8);
            qlf[kc][3] = *(const uint32_t*)(q8l + d0 + 8);
        }
    }

    float O[8][4] = {};
    float m_g = -1e30f, m_g8 = -1e30f, l_g = 0.f, l_g8 = 0.f;

    const int kr = tid >> 3, kc8 = tid & 7;
    const int vd = tid >> 2, vc = tid & 3;
    const __nv_bfloat16* khb = g_kph + (size_t)(b * SEQ) * EMB + h * HD;
    const __nv_bfloat16* klb = g_kpl + (size_t)(b * SEQ) * EMB + h * HD;
    const __nv_bfloat16* vhb = g_vth + (size_t)((b * NH + h) * HD) * SEQ;
    const __nv_bfloat16* vlb = g_vtl + (size_t)((b * NH + h) * HD) * SEQ;
    const uint32_t sKh = smem_u32(Ksh), sKl = smem_u32(Ksl);
    const uint32_t sVh = smem_u32(Vsh), sVl = smem_u32(Vsl);

    for (int j0 = 0; j0 < SEQ; j0 += 32) {
        {
            const __nv_bfloat16* ks = khb + (size_t)(j0 + kr) * EMB + kc8 * 8;
            const __nv_bfloat16* ls = klb + (size_t)(j0 + kr) * EMB + kc8 * 8;
            const uint32_t kd = kr * (FKP * 2) + kc8 * 16;
            CP_ASYNC16(sKh + kd, ks);
            CP_ASYNC16(sKl + kd, ls);
            const __nv_bfloat16* vs = vhb + (size_t)vd * SEQ + j0 + vc * 8;
            const __nv_bfloat16* ws = vlb + (size_t)vd * SEQ + j0 + vc * 8;
            const uint32_t vdd = vd * (FVP * 2) + vc * 16;
            CP_ASYNC16(sVh + vdd, vs);
            CP_ASYNC16(sVl + vdd, ws);
        }
        CP_COMMIT();
        CP_WAIT0();
        __syncthreads();

        // S = Q K^T
        float s[4][4] = {};
        #pragma unroll
        for (int kc = 0; kc < 4; kc++) {
            uint32_t bh_[4][2], bl_[4][2];
            #pragma unroll
            for (int nf = 0; nf < 4; nf++) {
                const int base = (nf * 8 + g) * FKP + kc * 16 + 2 * t;
                bh_[nf][0] = *(const uint32_t*)(Ksh + base);
                bh_[nf][1] = *(const uint32_t*)(Ksh + base + 8);
                bl_[nf][0] = *(const uint32_t*)(Ksl + base);
                bl_[nf][1] = *(const uint32_t*)(Ksl + base + 8);
            }
            #pragma unroll
            for (int nf = 0; nf < 4; nf++) {
                mma16816(s[nf], qhf[kc], bh_[nf]);
                mma16816(s[nf], qhf[kc], bl_[nf]);
                mma16816(s[nf], qlf[kc], bh_[nf]);
            }
        }

        // online softmax
        float mx0 = -1e30f, mx8 = -1e30f;
        #pragma unroll
        for (int nf = 0; nf < 4; nf++) {
            mx0 = fmaxf(mx0, fmaxf(s[nf][0], s[nf][1]));
            mx8 = fmaxf(mx8, fmaxf(s[nf][2], s[nf][3]));
        }
        mx0 = fmaxf(mx0, __shfl_xor_sync(0xffffffffu, mx0, 1));
        mx0 = fmaxf(mx0, __shfl_xor_sync(0xffffffffu, mx0, 2));
        mx8 = fmaxf(mx8, __shfl_xor_sync(0xffffffffu, mx8, 1));
        mx8 = fmaxf(mx8, __shfl_xor_sync(0xffffffffu, mx8, 2));
        const float mn_g = fmaxf(m_g, mx0), mn_g8 = fmaxf(m_g8, mx8);
        const float alpha_g = __expf(m_g - mn_g), alpha_g8 = __expf(m_g8 - mn_g8);
        m_g = mn_g; m_g8 = mn_g8;

        float p[4][4];
        float sum0 = 0.f, sum8 = 0.f;
        #pragma unroll
        for (int nf = 0; nf < 4; nf++) {
            p[nf][0] = __expf(s[nf][0] - mn_g);
            p[nf][1] = __expf(s[nf][1] - mn_g);
            p[nf][2] = __expf(s[nf][2] - mn_g8);
            p[nf][3] = __expf(s[nf][3] - mn_g8);
            sum0 += p[nf][0] + p[nf][1];
            sum8 += p[nf][2] + p[nf][3];
        }
        sum0 += __shfl_xor_sync(0xffffffffu, sum0, 1);
        sum0 += __shfl_xor_sync(0xffffffffu, sum0, 2);
        sum8 += __shfl_xor_sync(0xffffffffu, sum8, 1);
        sum8 += __shfl_xor_sync(0xffffffffu, sum8, 2);
        l_g  = l_g  * alpha_g  + sum0;
        l_g8 = l_g8 * alpha_g8 + sum8;

        #pragma unroll
        for (int nf2 = 0; nf2 < 8; nf2++) {
            O[nf2][0] *= alpha_g;  O[nf2][1] *= alpha_g;
            O[nf2][2] *= alpha_g8; O[nf2][3] *= alpha_g8;
        }

        // P fragments (S C-frag == PV A-frag layout)
        uint32_t pah[2][4], pal[2][4];
        #pragma unroll
        for (int kc2 = 0; kc2 < 2; kc2++) {
            const int nA = 2 * kc2, nB = 2 * kc2 + 1;
            split_pack2(p[nA][0], p[nA][1], pah[kc2][0], pal[kc2][0]);
            split_pack2(p[nA][2], p[nA][3], pah[kc2][1], pal[kc2][1]);
            split_pack2(p[nB][0], p[nB][1], pah[kc2][2], pal[kc2][2]);
            split_pack2(p[nB][2], p[nB][3], pah[kc2][3], pal[kc2][3]);
        }

        // O += P V
        #pragma unroll
        for (int nf2 = 0; nf2 < 8; nf2++) {
            #pragma unroll
            for (int kc2 = 0; kc2 < 2; kc2++) {
                const int base = (nf2 * 8 + g) * FVP + kc2 * 16 + 2 * t;
                uint32_t vbh[2], vbl[2];
                vbh[0] = *(const uint32_t*)(Vsh + base);
                vbh[1] = *(const uint32_t*)(Vsh + base + 8);
                vbl[0] = *(const uint32_t*)(Vsl + base);
                vbl[1] = *(const uint32_t*)(Vsl + base + 8);
                mma16816(O[nf2], pah[kc2], vbh);
                mma16816(O[nf2], pal[kc2], vbh);
                mma16816(O[nf2], pah[kc2], vbl);
            }
        }
        __syncthreads();
    }

    const float li_g = 1.0f / l_g, li_g8 = 1.0f / l_g8;
    const size_t row0 = (size_t)(b * SEQ + q0 + m0 + g) * EMB;
    const size_t row8 = row0 + (size_t)8 * EMB;
    #pragma unroll
    for (int nf2 = 0; nf2 < 8; nf2++) {
        const int col = h * HD + nf2 * 8 + 2 * t;
        uint32_t h01, l01, h23, l23;
        split_pack2(O[nf2][0] * li_g,  O[nf2][1] * li_g,  h01, l01);
        split_pack2(O[nf2][2] * li_g8, O[nf2][3] * li_g8, h23, l23);
        *(uint32_t*)(g_ch + row0 + col) = h01;
        *(uint32_t*)(g_cl + row0 + col) = l01;
        *(uint32_t*)(g_ch + row8 + col) = h23;
        *(uint32_t*)(g_cl + row8 + col) = l23;
    }
}

// ---------------------------------------------------------------------------
extern "C" void kernel_launch(void* const* d_in, const int* in_sizes, int n_in,
                              void* d_out, int out_size)
{
    const float* Q  = (const float*)d_in[0];
    const float* K  = (const float*)d_in[1];
    const float* V  = (const float*)d_in[2];
    const float* Wq = (const float*)d_in[3];
    const float* Wk = (const float*)d_in[4];
    const float* Wv = (const float*)d_in[5];
    const float* Wo = (const float*)d_in[6];
    float* out = (float*)d_out;

    // batched input splits (Q, K, V in one launch)
    const int n4 = MROWS * EMB / 4;
    const int sb = 256, sg = (n4 + sb - 1) / sb;
    split_bf16_3<<<dim3(sg, 3), sb>>>(Q, K, V, n4);

    // batched weight transposes (4 in one launch)
    dim3 tb(32, 8);
    transpose_split_4<<<dim3(EMB / 32, EMB / 32, 4), tb>>>(Wq, Wk, Wv, Wo);

    // batched Q/K/V projection GEMMs (768 blocks in one launch)
    gemm_qkv<<<dim3(EMB / 128, MROWS / 128, 3), 256>>>(MROWS, EMB, EMB);

    dim3 vt(SEQ / 32, HD / 32, BATCH * NH);    // (64, 2, 32)
    transpose_v<<<vt, tb>>>();

    dim3 ga(SEQ / 128, NH, BATCH);             // (16, 16, 2)
    flash_mma<<<ga, 256>>>();

    gemm_wo<<<dim3(EMB / 128, MROWS / 128), 256>>>(out, MROWS, EMB, EMB);
}

// round 12
// speedup vs baseline: 1.2059x; 1.0801x over previous
#include <cuda_runtime.h>
#include <cuda_bf16.h>
#include <cuda_fp16.h>
#include <cstdint>
#include <cstring>

#define BATCH 2
#define SEQ   2048
#define EMB   1024
#define NH    16
#define HD    64
#define MROWS (BATCH*SEQ)   // 4096

// ---------------------------------------------------------------------------
// Scratch (static device globals — allocation guards forbid cudaMalloc).
// All kernels reference these symbols DIRECTLY (no runtime pointer passing).
// ---------------------------------------------------------------------------
__device__ __nv_bfloat16 g_qh[MROWS * EMB], g_ql[MROWS * EMB];
__device__ __nv_bfloat16 g_kh[MROWS * EMB], g_kl[MROWS * EMB];
__device__ __nv_bfloat16 g_vh[MROWS * EMB], g_vl[MROWS * EMB];
__device__ __nv_bfloat16 g_qph[MROWS * EMB], g_qpl[MROWS * EMB];
__device__ __nv_bfloat16 g_kph[MROWS * EMB], g_kpl[MROWS * EMB];
__device__ __nv_bfloat16 g_vph[MROWS * EMB], g_vpl[MROWS * EMB];
__device__ __half        g_vth[MROWS * EMB], g_vtl[MROWS * EMB];   // fp16 V^T hi/lo
__device__ __nv_bfloat16 g_ch[MROWS * EMB], g_cl[MROWS * EMB];
__device__ __nv_bfloat16 g_wqh[EMB * EMB], g_wql[EMB * EMB];
__device__ __nv_bfloat16 g_wkh[EMB * EMB], g_wkl[EMB * EMB];
__device__ __nv_bfloat16 g_wvh[EMB * EMB], g_wvl[EMB * EMB];
__device__ __nv_bfloat16 g_woh[EMB * EMB], g_wol[EMB * EMB];

// ---------------------------------------------------------------------------
// Helpers
// ---------------------------------------------------------------------------
__device__ __forceinline__ uint32_t smem_u32(const void* p) {
    uint32_t a;
    asm("{ .reg .u64 t; cvta.to.shared.u64 t, %1; cvt.u32.u64 %0, t; }" : "=r"(a) : "l"(p));
    return a;
}

#define CP_ASYNC16(dst, src) \
    asm volatile("cp.async.cg.shared.global [%0], [%1], 16;" :: "r"((uint32_t)(dst)), "l"(src))
#define CP_COMMIT() asm volatile("cp.async.commit_group;" ::: "memory")
#define CP_WAIT0()  asm volatile("cp.async.wait_group 0;" ::: "memory")

// mma.sync m16n8k16 bf16 -> f32
__device__ __forceinline__ void mma16816(float* c, const uint32_t* a, const uint32_t* b) {
    asm volatile(
        "mma.sync.aligned.m16n8k16.row.col.f32.bf16.bf16.f32 "
        "{%0,%1,%2,%3}, {%4,%5,%6,%7}, {%8,%9}, {%0,%1,%2,%3};"
        : "+f"(c[0]), "+f"(c[1]), "+f"(c[2]), "+f"(c[3])
        : "r"(a[0]), "r"(a[1]), "r"(a[2]), "r"(a[3]), "r"(b[0]), "r"(b[1]));
}
// mma.sync m16n8k16 fp16 -> f32
__device__ __forceinline__ void mma16816h(float* c, const uint32_t* a, const uint32_t* b) {
    asm volatile(
        "mma.sync.aligned.m16n8k16.row.col.f32.f16.f16.f32 "
        "{%0,%1,%2,%3}, {%4,%5,%6,%7}, {%8,%9}, {%0,%1,%2,%3};"
        : "+f"(c[0]), "+f"(c[1]), "+f"(c[2]), "+f"(c[3])
        : "r"(a[0]), "r"(a[1]), "r"(a[2]), "r"(a[3]), "r"(b[0]), "r"(b[1]));
}

__device__ __forceinline__ void split1(float x, __nv_bfloat16& h, __nv_bfloat16& l) {
    h = __float2bfloat16_rn(x);
    l = __float2bfloat16_rn(x - __bfloat162float(h));
}
__device__ __forceinline__ uint32_t pack2(__nv_bfloat16 a, __nv_bfloat16 b) {
    return (uint32_t)__bfloat16_as_ushort(a) | ((uint32_t)__bfloat16_as_ushort(b) << 16);
}
__device__ __forceinline__ void split_pack2(float x0, float x1, uint32_t& hi, uint32_t& lo) {
    __nv_bfloat16 h0, l0, h1, l1;
    split1(x0, h0, l0); split1(x1, h1, l1);
    hi = pack2(h0, h1); lo = pack2(l0, l1);
}
// pack two floats into fp16x2 (x0 in low half, matching k=2t lane order)
__device__ __forceinline__ uint32_t packh2(float x0, float x1) {
    __half2 h = __float22half2_rn(make_float2(x0, x1));
    uint32_t u;
    memcpy(&u, &h, 4);
    return u;
}

// ---------------------------------------------------------------------------
// Pre-pass 1: batched bf16 hi/lo split of Q,K,V (grid.y in {0,1,2})
// ---------------------------------------------------------------------------
__global__ void split_bf16_3(const float* __restrict__ Q, const float* __restrict__ K,
                             const float* __restrict__ V, int n4) {
    const int z = blockIdx.y;
    int i = blockIdx.x * blockDim.x + threadIdx.x;
    if (i >= n4) return;
    const float* x;
    __nv_bfloat16 *hi, *lo;
    switch (z) {
        case 0:  x = Q; hi = g_qh; lo = g_ql; break;
        case 1:  x = K; hi = g_kh; lo = g_kl; break;
        default: x = V; hi = g_vh; lo = g_vl; break;
    }
    float4 v = ((const float4*)x)[i];
    uint32_t h01, l01, h23, l23;
    split_pack2(v.x, v.y, h01, l01);
    split_pack2(v.z, v.w, h23, l23);
    ((uint2*)hi)[i] = make_uint2(h01, h23);
    ((uint2*)lo)[i] = make_uint2(l01, l23);
}

// ---------------------------------------------------------------------------
// Pre-pass 2: batched W[K][N] -> Wt hi/lo [N][K] (grid.z in {0..3})
// ---------------------------------------------------------------------------
__global__ void transpose_split_4(const float* __restrict__ Wq, const float* __restrict__ Wk,
                                  const float* __restrict__ Wv, const float* __restrict__ Wo) {
    __shared__ float t[32][33];
    const float* W;
    __nv_bfloat16 *Thi, *Tlo;
    switch (blockIdx.z) {
        case 0:  W = Wq; Thi = g_wqh; Tlo = g_wql; break;
        case 1:  W = Wk; Thi = g_wkh; Tlo = g_wkl; break;
        case 2:  W = Wv; Thi = g_wvh; Tlo = g_wvl; break;
        default: W = Wo; Thi = g_woh; Tlo = g_wol; break;
    }
    int x = blockIdx.x * 32 + threadIdx.x;
    int y = blockIdx.y * 32 + threadIdx.y;
    #pragma unroll
    for (int i = 0; i < 32; i += 8)
        t[threadIdx.y + i][threadIdx.x] = W[(size_t)(y + i) * EMB + x];
    __syncthreads();
    int nx = blockIdx.y * 32 + threadIdx.x;
    int ny = blockIdx.x * 32 + threadIdx.y;
    #pragma unroll
    for (int i = 0; i < 32; i += 8) {
        float v = t[threadIdx.x][threadIdx.y + i];
        __nv_bfloat16 h, l;
        split1(v, h, l);
        Thi[(size_t)(ny + i) * EMB + nx] = h;
        Tlo[(size_t)(ny + i) * EMB + nx] = l;
    }
}

// ---------------------------------------------------------------------------
// V transpose: recombine bf16 hi/lo -> float -> fp16 hi/lo, transposed
// [b*S+s][h*64+d] -> [(b*16+h)*64+d][s]
// ---------------------------------------------------------------------------
__global__ void transpose_v() {
    __shared__ float a[32][33];
    const int bh = blockIdx.z;
    const int b = bh >> 4, h = bh & 15;
    const int s0 = blockIdx.x * 32, d0 = blockIdx.y * 32;
    const int tx = threadIdx.x, ty = threadIdx.y;
    #pragma unroll
    for (int i = 0; i < 32; i += 8) {
        size_t src = (size_t)(b * SEQ + s0 + ty + i) * EMB + h * HD + d0 + tx;
        a[ty + i][tx] = __bfloat162float(g_vph[src]) + __bfloat162float(g_vpl[src]);
    }
    __syncthreads();
    #pragma unroll
    for (int i = 0; i < 32; i += 8) {
        size_t dst = (size_t)(bh * HD + d0 + ty + i) * SEQ + s0 + tx;
        float v = a[tx][ty + i];
        __half hh = __float2half_rn(v);
        g_vth[dst] = hh;
        g_vtl[dst] = __float2half_rn(v - __half2float(hh));
    }
}

// ---------------------------------------------------------------------------
// mma.sync 3x-bf16 GEMM core (round-7 proven): block 128x128, BK=32,
// 256 threads (8 warps 2x4, warp tile 64x32), single-stage cp.async.
// SMEM: 4 tiles x 128 rows x 20 words = 40960 B static (in caller).
// ---------------------------------------------------------------------------
#define TW 20
#define TILE_W (128 * TW)

__device__ __forceinline__ void gemm_core(
    const __nv_bfloat16* __restrict__ Ahi, const __nv_bfloat16* __restrict__ Alo,
    const __nv_bfloat16* __restrict__ Bhi, const __nv_bfloat16* __restrict__ Blo,
    float* __restrict__ Cf, __nv_bfloat16* __restrict__ Chi,
    __nv_bfloat16* __restrict__ Clo, float scale, int M, int N, int K,
    uint32_t* sm)
{
    const int tid = threadIdx.x;
    const int wid = tid >> 5, lane = tid & 31;
    const int g = lane >> 2, t = lane & 3;
    const int wm = wid & 1, wn = wid >> 1;
    const int bm = blockIdx.y * 128, bn = blockIdx.x * 128;

    const uint32_t sbase = smem_u32(sm);
    const int r0 = tid >> 2, c0 = tid & 3;
    const __nv_bfloat16* gsrc[4] = {
        Ahi + (size_t)bm * K, Alo + (size_t)bm * K,
        Bhi + (size_t)bn * K, Blo + (size_t)bn * K
    };

    float acc[4][4][4] = {};

    const int NS = K / 32;
    for (int s = 0; s < NS; s++) {
        const int k0 = s * 32;
        #pragma unroll
        for (int tile = 0; tile < 4; tile++) {
            const __nv_bfloat16* src = gsrc[tile] + (size_t)r0 * K + k0 + c0 * 8;
            uint32_t d = sbase + (tile * TILE_W + r0 * TW + c0 * 4) * 4;
            CP_ASYNC16(d, src);
            CP_ASYNC16(d + 64 * TW * 4, src + (size_t)64 * K);
        }
        CP_COMMIT();
        CP_WAIT0();
        __syncthreads();

        const uint32_t* As  = sm + 0 * TILE_W;
        const uint32_t* Als = sm + 1 * TILE_W;
        const uint32_t* Bs  = sm + 2 * TILE_W;
        const uint32_t* Bls = sm + 3 * TILE_W;

        #pragma unroll
        for (int kk = 0; kk < 2; kk++) {
            const int kw = kk * 8;
            uint32_t ah[4][4], al[4][4], bh[4][2], bl[4][2];
            #pragma unroll
            for (int mf = 0; mf < 4; mf++) {
                const int m0 = wm * 64 + mf * 16;
                const int i0 = (m0 + g) * TW + t + kw;
                const int i8 = (m0 + g + 8) * TW + t + kw;
                ah[mf][0] = As[i0];  ah[mf][1] = As[i8];
                ah[mf][2] = As[i0 + 4]; ah[mf][3] = As[i8 + 4];
                al[mf][0] = Als[i0]; al[mf][1] = Als[i8];
                al[mf][2] = Als[i0 + 4]; al[mf][3] = Als[i8 + 4];
            }
            #pragma unroll
            for (int nf = 0; nf < 4; nf++) {
                const int n0 = wn * 32 + nf * 8;
                const int j0 = (n0 + g) * TW + t + kw;
                bh[nf][0] = Bs[j0];  bh[nf][1] = Bs[j0 + 4];
                bl[nf][0] = Bls[j0]; bl[nf][1] = Bls[j0 + 4];
            }
            #pragma unroll
            for (int mf = 0; mf < 4; mf++)
                #pragma unroll
                for (int nf = 0; nf < 4; nf++) {
                    mma16816(acc[mf][nf], ah[mf], bh[nf]);
                    mma16816(acc[mf][nf], ah[mf], bl[nf]);
                    mma16816(acc[mf][nf], al[mf], bh[nf]);
                }
        }
        __syncthreads();
    }

    #pragma unroll
    for (int mf = 0; mf < 4; mf++) {
        const int m = bm + wm * 64 + mf * 16 + g;
        #pragma unroll
        for (int nf = 0; nf < 4; nf++) {
            const int n = bn + wn * 32 + nf * 8 + 2 * t;
            float v0 = acc[mf][nf][0], v1 = acc[mf][nf][1];
            float v2 = acc[mf][nf][2], v3 = acc[mf][nf][3];
            if (Cf) {
                *(float2*)(Cf + (size_t)m * N + n)       = make_float2(v0, v1);
                *(float2*)(Cf + (size_t)(m + 8) * N + n) = make_float2(v2, v3);
            }
            if (Chi) {
                uint32_t h01, l01, h23, l23;
                split_pack2(v0 * scale, v1 * scale, h01, l01);
                split_pack2(v2 * scale, v3 * scale, h23, l23);
                *(uint32_t*)(Chi + (size_t)m * N + n)       = h01;
                *(uint32_t*)(Clo + (size_t)m * N + n)       = l01;
                *(uint32_t*)(Chi + (size_t)(m + 8) * N + n) = h23;
                *(uint32_t*)(Clo + (size_t)(m + 8) * N + n) = l23;
            }
        }
    }
}

// Batched Q/K/V projection GEMM: grid.z selects tensor set via global symbols.
__global__ __launch_bounds__(256) void gemm_qkv(int M, int N, int K) {
    __shared__ uint32_t sm[4 * TILE_W];
    const __nv_bfloat16 *Ahi, *Alo, *Bhi, *Blo;
    __nv_bfloat16 *Chi, *Clo;
    float scale;
    switch (blockIdx.z) {
        case 0:  Ahi = g_qh; Alo = g_ql; Bhi = g_wqh; Blo = g_wql;
                 Chi = g_qph; Clo = g_qpl; scale = 0.125f; break;
        case 1:  Ahi = g_kh; Alo = g_kl; Bhi = g_wkh; Blo = g_wkl;
                 Chi = g_kph; Clo = g_kpl; scale = 1.0f; break;
        default: Ahi = g_vh; Alo = g_vl; Bhi = g_wvh; Blo = g_wvl;
                 Chi = g_vph; Clo = g_vpl; scale = 1.0f; break;
    }
    gemm_core(Ahi, Alo, Bhi, Blo, nullptr, Chi, Clo, scale, M, N, K, sm);
}

__global__ __launch_bounds__(256) void gemm_wo(float* __restrict__ Cf,
                                               int M, int N, int K) {
    __shared__ uint32_t sm[4 * TILE_W];
    gemm_core(g_ch, g_cl, g_woh, g_wol, Cf, nullptr, nullptr, 1.0f, M, N, K, sm);
}

// ---------------------------------------------------------------------------
// Flash attention on mma.sync: 128 queries/block, 8 warps, KV tile = 32,
// single-buffered. QK^T: bf16 3-term. PV: fp16, P unsplit (2 MMAs).
// SMEM 19456 B static.
// ---------------------------------------------------------------------------
#define FKP 72
#define FVP 40

__global__ __launch_bounds__(256) void flash_mma() {
    __shared__ __nv_bfloat16 Ksh[32 * FKP], Ksl[32 * FKP];
    __shared__ __half        Vsh[64 * FVP], Vsl[64 * FVP];

    const int tid = threadIdx.x, wid = tid >> 5, lane = tid & 31;
    const int g = lane >> 2, t = lane & 3;
    const int qt = blockIdx.x, h = blockIdx.y, b = blockIdx.z;
    const int q0 = qt * 128, m0 = wid * 16;

    uint32_t qhf[4][4], qlf[4][4];
    {
        const size_t rbase = (size_t)(b * SEQ + q0 + m0 + g) * EMB + h * HD;
        const __nv_bfloat16* q0h = g_qph + rbase;
        const __nv_bfloat16* q8h = q0h + (size_t)8 * EMB;
        const __nv_bfloat16* q0l = g_qpl + rbase;
        const __nv_bfloat16* q8l = q0l + (size_t)8 * EMB;
        #pragma unroll
        for (int kc = 0; kc < 4; kc++) {
            const int d0 = kc * 16 + 2 * t;
            qhf[kc][0] = *(const uint32_t*)(q0h + d0);
            qhf[kc][1] = *(const uint32_t*)(q8h + d0);
            qhf[kc][2] = *(const uint32_t*)(q0h + d0 + 8);
            qhf[kc][3] = *(const uint32_t*)(q8h + d0 + 8);
            qlf[kc][0] = *(const uint32_t*)(q0l + d0);
            qlf[kc][1] = *(const uint32_t*)(q8l + d0);
            qlf[kc][2] = *(const uint32_t*)(q0l + d0 + 8);
            qlf[kc][3] = *(const uint32_t*)(q8l + d0 + 8);
        }
    }

    float O[8][4] = {};
    float m_g = -1e30f, m_g8 = -1e30f, l_g = 0.f, l_g8 = 0.f;

    const int kr = tid >> 3, kc8 = tid & 7;
    const int vd = tid >> 2, vc = tid & 3;
    const __nv_bfloat16* khb = g_kph + (size_t)(b * SEQ) * EMB + h * HD;
    const __nv_bfloat16* klb = g_kpl + (size_t)(b * SEQ) * EMB + h * HD;
    const __half* vhb = g_vth + (size_t)((b * NH + h) * HD) * SEQ;
    const __half* vlb = g_vtl + (size_t)((b * NH + h) * HD) * SEQ;
    const uint32_t sKh = smem_u32(Ksh), sKl = smem_u32(Ksl);
    const uint32_t sVh = smem_u32(Vsh), sVl = smem_u32(Vsl);

    for (int j0 = 0; j0 < SEQ; j0 += 32) {
        {
            const __nv_bfloat16* ks = khb + (size_t)(j0 + kr) * EMB + kc8 * 8;
            const __nv_bfloat16* ls = klb + (size_t)(j0 + kr) * EMB + kc8 * 8;
            const uint32_t kd = kr * (FKP * 2) + kc8 * 16;
            CP_ASYNC16(sKh + kd, ks);
            CP_ASYNC16(sKl + kd, ls);
            const __half* vs = vhb + (size_t)vd * SEQ + j0 + vc * 8;
            const __half* ws = vlb + (size_t)vd * SEQ + j0 + vc * 8;
            const uint32_t vdd = vd * (FVP * 2) + vc * 16;
            CP_ASYNC16(sVh + vdd, vs);
            CP_ASYNC16(sVl + vdd, ws);
        }
        CP_COMMIT();
        CP_WAIT0();
        __syncthreads();

        // S = Q K^T  (bf16 3-term)
        float s[4][4] = {};
        #pragma unroll
        for (int kc = 0; kc < 4; kc++) {
            uint32_t bh_[4][2], bl_[4][2];
            #pragma unroll
            for (int nf = 0; nf < 4; nf++) {
                const int base = (nf * 8 + g) * FKP + kc * 16 + 2 * t;
                bh_[nf][0] = *(const uint32_t*)(Ksh + base);
                bh_[nf][1] = *(const uint32_t*)(Ksh + base + 8);
                bl_[nf][0] = *(const uint32_t*)(Ksl + base);
                bl_[nf][1] = *(const uint32_t*)(Ksl + base + 8);
            }
            #pragma unroll
            for (int nf = 0; nf < 4; nf++) {
                mma16816(s[nf], qhf[kc], bh_[nf]);
                mma16816(s[nf], qhf[kc], bl_[nf]);
                mma16816(s[nf], qlf[kc], bh_[nf]);
            }
        }

        // online softmax
        float mx0 = -1e30f, mx8 = -1e30f;
        #pragma unroll
        for (int nf = 0; nf < 4; nf++) {
            mx0 = fmaxf(mx0, fmaxf(s[nf][0], s[nf][1]));
            mx8 = fmaxf(mx8, fmaxf(s[nf][2], s[nf][3]));
        }
        mx0 = fmaxf(mx0, __shfl_xor_sync(0xffffffffu, mx0, 1));
        mx0 = fmaxf(mx0, __shfl_xor_sync(0xffffffffu, mx0, 2));
        mx8 = fmaxf(mx8, __shfl_xor_sync(0xffffffffu, mx8, 1));
        mx8 = fmaxf(mx8, __shfl_xor_sync(0xffffffffu, mx8, 2));
        const float mn_g = fmaxf(m_g, mx0), mn_g8 = fmaxf(m_g8, mx8);
        const float alpha_g = __expf(m_g - mn_g), alpha_g8 = __expf(m_g8 - mn_g8);
        m_g = mn_g; m_g8 = mn_g8;

        float p[4][4];
        float sum0 = 0.f, sum8 = 0.f;
        #pragma unroll
        for (int nf = 0; nf < 4; nf++) {
            p[nf][0] = __expf(s[nf][0] - mn_g);
            p[nf][1] = __expf(s[nf][1] - mn_g);
            p[nf][2] = __expf(s[nf][2] - mn_g8);
            p[nf][3] = __expf(s[nf][3] - mn_g8);
            sum0 += p[nf][0] + p[nf][1];
            sum8 += p[nf][2] + p[nf][3];
        }
        sum0 += __shfl_xor_sync(0xffffffffu, sum0, 1);
        sum0 += __shfl_xor_sync(0xffffffffu, sum0, 2);
        sum8 += __shfl_xor_sync(0xffffffffu, sum8, 1);
        sum8 += __shfl_xor_sync(0xffffffffu, sum8, 2);
        l_g  = l_g  * alpha_g  + sum0;
        l_g8 = l_g8 * alpha_g8 + sum8;

        #pragma unroll
        for (int nf2 = 0; nf2 < 8; nf2++) {
            O[nf2][0] *= alpha_g;  O[nf2][1] *= alpha_g;
            O[nf2][2] *= alpha_g8; O[nf2][3] *= alpha_g8;
        }

        // P fragments: fp16, no split (S C-frag == PV A-frag layout)
        uint32_t pf[2][4];
        #pragma unroll
        for (int kc2 = 0; kc2 < 2; kc2++) {
            const int nA = 2 * kc2, nB = 2 * kc2 + 1;
            pf[kc2][0] = packh2(p[nA][0], p[nA][1]);
            pf[kc2][1] = packh2(p[nA][2], p[nA][3]);
            pf[kc2][2] = packh2(p[nB][0], p[nB][1]);
            pf[kc2][3] = packh2(p[nB][2], p[nB][3]);
        }

        // O += P V  (fp16: 2 MMAs per tile instead of 3)
        #pragma unroll
        for (int nf2 = 0; nf2 < 8; nf2++) {
            #pragma unroll
            for (int kc2 = 0; kc2 < 2; kc2++) {
                const int base = (nf2 * 8 + g) * FVP + kc2 * 16 + 2 * t;
                uint32_t vbh[2], vbl[2];
                vbh[0] = *(const uint32_t*)(Vsh + base);
                vbh[1] = *(const uint32_t*)(Vsh + base + 8);
                vbl[0] = *(const uint32_t*)(Vsl + base);
                vbl[1] = *(const uint32_t*)(Vsl + base + 8);
                mma16816h(O[nf2], pf[kc2], vbh);
                mma16816h(O[nf2], pf[kc2], vbl);
            }
        }
        __syncthreads();
    }

    const float li_g = 1.0f / l_g, li_g8 = 1.0f / l_g8;
    const size_t row0 = (size_t)(b * SEQ + q0 + m0 + g) * EMB;
    const size_t row8 = row0 + (size_t)8 * EMB;
    #pragma unroll
    for (int nf2 = 0; nf2 < 8; nf2++) {
        const int col = h * HD + nf2 * 8 + 2 * t;
        uint32_t h01, l01, h23, l23;
        split_pack2(O[nf2][0] * li_g,  O[nf2][1] * li_g,  h01, l01);
        split_pack2(O[nf2][2] * li_g8, O[nf2][3] * li_g8, h23, l23);
        *(uint32_t*)(g_ch + row0 + col) = h01;
        *(uint32_t*)(g_cl + row0 + col) = l01;
        *(uint32_t*)(g_ch + row8 + col) = h23;
        *(uint32_t*)(g_cl + row8 + col) = l23;
    }
}

// ---------------------------------------------------------------------------
extern "C" void kernel_launch(void* const* d_in, const int* in_sizes, int n_in,
                              void* d_out, int out_size)
{
    const float* Q  = (const float*)d_in[0];
    const float* K  = (const float*)d_in[1];
    const float* V  = (const float*)d_in[2];
    const float* Wq = (const float*)d_in[3];
    const float* Wk = (const float*)d_in[4];
    const float* Wv = (const float*)d_in[5];
    const float* Wo = (const float*)d_in[6];
    float* out = (float*)d_out;

    const int n4 = MROWS * EMB / 4;
    const int sb = 256, sg = (n4 + sb - 1) / sb;
    split_bf16_3<<<dim3(sg, 3), sb>>>(Q, K, V, n4);

    dim3 tb(32, 8);
    transpose_split_4<<<dim3(EMB / 32, EMB / 32, 4), tb>>>(Wq, Wk, Wv, Wo);

    gemm_qkv<<<dim3(EMB / 128, MROWS / 128, 3), 256>>>(MROWS, EMB, EMB);

    dim3 vt(SEQ / 32, HD / 32, BATCH * NH);    // (64, 2, 32)
    transpose_v<<<vt, tb>>>();

    dim3 ga(SEQ / 128, NH, BATCH);             // (16, 16, 2)
    flash_mma<<<ga, 256>>>();

    gemm_wo<<<dim3(EMB / 128, MROWS / 128), 256>>>(out, MROWS, EMB, EMB);
}

// round 13
// speedup vs baseline: 1.3177x; 1.0928x over previous
#include <cuda_runtime.h>
#include <cuda_bf16.h>
#include <cuda_fp16.h>
#include <cstdint>
#include <cstring>

#define BATCH 2
#define SEQ   2048
#define EMB   1024
#define NH    16
#define HD    64
#define MROWS (BATCH*SEQ)   // 4096

// ---------------------------------------------------------------------------
// Scratch (static device globals). All kernels reference symbols directly.
// ---------------------------------------------------------------------------
__device__ __nv_bfloat16 g_qh[MROWS * EMB], g_ql[MROWS * EMB];
__device__ __nv_bfloat16 g_kh[MROWS * EMB], g_kl[MROWS * EMB];
__device__ __nv_bfloat16 g_vh[MROWS * EMB], g_vl[MROWS * EMB];
__device__ __half        g_qph[MROWS * EMB], g_qpl[MROWS * EMB];   // Q proj, fp16 2-term, pre-scaled
__device__ __half        g_kp [MROWS * EMB];                        // K proj, fp16 single
__device__ __half        g_vph[MROWS * EMB], g_vpl[MROWS * EMB];   // V proj, fp16 2-term
__device__ __half        g_vth[MROWS * EMB], g_vtl[MROWS * EMB];   // fp16 V^T hi/lo
__device__ __nv_bfloat16 g_ch[MROWS * EMB], g_cl[MROWS * EMB];     // attn out, bf16 2-term
__device__ __nv_bfloat16 g_wqh[EMB * EMB], g_wql[EMB * EMB];
__device__ __nv_bfloat16 g_wkh[EMB * EMB], g_wkl[EMB * EMB];
__device__ __nv_bfloat16 g_wvh[EMB * EMB], g_wvl[EMB * EMB];
__device__ __nv_bfloat16 g_woh[EMB * EMB], g_wol[EMB * EMB];

// ---------------------------------------------------------------------------
// Helpers
// ---------------------------------------------------------------------------
__device__ __forceinline__ uint32_t smem_u32(const void* p) {
    uint32_t a;
    asm("{ .reg .u64 t; cvta.to.shared.u64 t, %1; cvt.u32.u64 %0, t; }" : "=r"(a) : "l"(p));
    return a;
}

#define CP_ASYNC16(dst, src) \
    asm volatile("cp.async.cg.shared.global [%0], [%1], 16;" :: "r"((uint32_t)(dst)), "l"(src))
#define CP_COMMIT() asm volatile("cp.async.commit_group;" ::: "memory")
#define CP_WAIT0()  asm volatile("cp.async.wait_group 0;" ::: "memory")

// mma.sync m16n8k16 bf16 -> f32
__device__ __forceinline__ void mma16816(float* c, const uint32_t* a, const uint32_t* b) {
    asm volatile(
        "mma.sync.aligned.m16n8k16.row.col.f32.bf16.bf16.f32 "
        "{%0,%1,%2,%3}, {%4,%5,%6,%7}, {%8,%9}, {%0,%1,%2,%3};"
        : "+f"(c[0]), "+f"(c[1]), "+f"(c[2]), "+f"(c[3])
        : "r"(a[0]), "r"(a[1]), "r"(a[2]), "r"(a[3]), "r"(b[0]), "r"(b[1]));
}
// mma.sync m16n8k16 fp16 -> f32
__device__ __forceinline__ void mma16816h(float* c, const uint32_t* a, const uint32_t* b) {
    asm volatile(
        "mma.sync.aligned.m16n8k16.row.col.f32.f16.f16.f32 "
        "{%0,%1,%2,%3}, {%4,%5,%6,%7}, {%8,%9}, {%0,%1,%2,%3};"
        : "+f"(c[0]), "+f"(c[1]), "+f"(c[2]), "+f"(c[3])
        : "r"(a[0]), "r"(a[1]), "r"(a[2]), "r"(a[3]), "r"(b[0]), "r"(b[1]));
}

__device__ __forceinline__ void split1(float x, __nv_bfloat16& h, __nv_bfloat16& l) {
    h = __float2bfloat16_rn(x);
    l = __float2bfloat16_rn(x - __bfloat162float(h));
}
__device__ __forceinline__ uint32_t pack2(__nv_bfloat16 a, __nv_bfloat16 b) {
    return (uint32_t)__bfloat16_as_ushort(a) | ((uint32_t)__bfloat16_as_ushort(b) << 16);
}
__device__ __forceinline__ void split_pack2(float x0, float x1, uint32_t& hi, uint32_t& lo) {
    __nv_bfloat16 h0, l0, h1, l1;
    split1(x0, h0, l0); split1(x1, h1, l1);
    hi = pack2(h0, h1); lo = pack2(l0, l1);
}
__device__ __forceinline__ uint32_t packh2(float x0, float x1) {
    __half2 h = __float22half2_rn(make_float2(x0, x1));
    uint32_t u;
    memcpy(&u, &h, 4);
    return u;
}
// fp16 2-term split of a float pair, packed
__device__ __forceinline__ void split_pack2h(float x0, float x1, uint32_t& hi, uint32_t& lo) {
    __half h0 = __float2half_rn(x0), h1 = __float2half_rn(x1);
    float l0 = x0 - __half2float(h0), l1 = x1 - __half2float(h1);
    __half2 hh, ll;
    hh = __halves2half2(h0, h1);
    ll = __floats2half2_rn(l0, l1);
    memcpy(&hi, &hh, 4);
    memcpy(&lo, &ll, 4);
}

// ---------------------------------------------------------------------------
// Pre-pass 1: batched bf16 hi/lo split of Q,K,V (grid.y in {0,1,2})
// ---------------------------------------------------------------------------
__global__ void split_bf16_3(const float* __restrict__ Q, const float* __restrict__ K,
                             const float* __restrict__ V, int n4) {
    const int z = blockIdx.y;
    int i = blockIdx.x * blockDim.x + threadIdx.x;
    if (i >= n4) return;
    const float* x;
    __nv_bfloat16 *hi, *lo;
    switch (z) {
        case 0:  x = Q; hi = g_qh; lo = g_ql; break;
        case 1:  x = K; hi = g_kh; lo = g_kl; break;
        default: x = V; hi = g_vh; lo = g_vl; break;
    }
    float4 v = ((const float4*)x)[i];
    uint32_t h01, l01, h23, l23;
    split_pack2(v.x, v.y, h01, l01);
    split_pack2(v.z, v.w, h23, l23);
    ((uint2*)hi)[i] = make_uint2(h01, h23);
    ((uint2*)lo)[i] = make_uint2(l01, l23);
}

// ---------------------------------------------------------------------------
// Pre-pass 2: batched W[K][N] -> Wt hi/lo [N][K] (grid.z in {0..3})
// ---------------------------------------------------------------------------
__global__ void transpose_split_4(const float* __restrict__ Wq, const float* __restrict__ Wk,
                                  const float* __restrict__ Wv, const float* __restrict__ Wo) {
    __shared__ float t[32][33];
    const float* W;
    __nv_bfloat16 *Thi, *Tlo;
    switch (blockIdx.z) {
        case 0:  W = Wq; Thi = g_wqh; Tlo = g_wql; break;
        case 1:  W = Wk; Thi = g_wkh; Tlo = g_wkl; break;
        case 2:  W = Wv; Thi = g_wvh; Tlo = g_wvl; break;
        default: W = Wo; Thi = g_woh; Tlo = g_wol; break;
    }
    int x = blockIdx.x * 32 + threadIdx.x;
    int y = blockIdx.y * 32 + threadIdx.y;
    #pragma unroll
    for (int i = 0; i < 32; i += 8)
        t[threadIdx.y + i][threadIdx.x] = W[(size_t)(y + i) * EMB + x];
    __syncthreads();
    int nx = blockIdx.y * 32 + threadIdx.x;
    int ny = blockIdx.x * 32 + threadIdx.y;
    #pragma unroll
    for (int i = 0; i < 32; i += 8) {
        float v = t[threadIdx.x][threadIdx.y + i];
        __nv_bfloat16 h, l;
        split1(v, h, l);
        Thi[(size_t)(ny + i) * EMB + nx] = h;
        Tlo[(size_t)(ny + i) * EMB + nx] = l;
    }
}

// ---------------------------------------------------------------------------
// V transpose: recombine fp16 hi/lo -> float -> fp16 hi/lo, transposed
// ---------------------------------------------------------------------------
__global__ void transpose_v() {
    __shared__ float a[32][33];
    const int bh = blockIdx.z;
    const int b = bh >> 4, h = bh & 15;
    const int s0 = blockIdx.x * 32, d0 = blockIdx.y * 32;
    const int tx = threadIdx.x, ty = threadIdx.y;
    #pragma unroll
    for (int i = 0; i < 32; i += 8) {
        size_t src = (size_t)(b * SEQ + s0 + ty + i) * EMB + h * HD + d0 + tx;
        a[ty + i][tx] = __half2float(g_vph[src]) + __half2float(g_vpl[src]);
    }
    __syncthreads();
    #pragma unroll
    for (int i = 0; i < 32; i += 8) {
        size_t dst = (size_t)(bh * HD + d0 + ty + i) * SEQ + s0 + tx;
        float v = a[tx][ty + i];
        __half hh = __float2half_rn(v);
        g_vth[dst] = hh;
        g_vtl[dst] = __float2half_rn(v - __half2float(hh));
    }
}

// ---------------------------------------------------------------------------
// mma.sync 3x-bf16 GEMM core: block 128x128, BK=32, 256 threads, 8 warps 2x4.
// SMEM: 4 tiles x 128 rows x 20 words = 40960 B static (in caller).
// Epilogue variants: fp32 (Cf), fp16 split (H1+H2), fp16 single (H1 only).
// ---------------------------------------------------------------------------
#define TW 20
#define TILE_W (128 * TW)

__device__ __forceinline__ void gemm_core(
    const __nv_bfloat16* __restrict__ Ahi, const __nv_bfloat16* __restrict__ Alo,
    const __nv_bfloat16* __restrict__ Bhi, const __nv_bfloat16* __restrict__ Blo,
    float* __restrict__ Cf, __half* __restrict__ H1, __half* __restrict__ H2,
    float scale, int M, int N, int K, uint32_t* sm)
{
    const int tid = threadIdx.x;
    const int wid = tid >> 5, lane = tid & 31;
    const int g = lane >> 2, t = lane & 3;
    const int wm = wid & 1, wn = wid >> 1;
    const int bm = blockIdx.y * 128, bn = blockIdx.x * 128;

    const uint32_t sbase = smem_u32(sm);
    const int r0 = tid >> 2, c0 = tid & 3;
    const __nv_bfloat16* gsrc[4] = {
        Ahi + (size_t)bm * K, Alo + (size_t)bm * K,
        Bhi + (size_t)bn * K, Blo + (size_t)bn * K
    };

    float acc[4][4][4] = {};

    const int NS = K / 32;
    for (int s = 0; s < NS; s++) {
        const int k0 = s * 32;
        #pragma unroll
        for (int tile = 0; tile < 4; tile++) {
            const __nv_bfloat16* src = gsrc[tile] + (size_t)r0 * K + k0 + c0 * 8;
            uint32_t d = sbase + (tile * TILE_W + r0 * TW + c0 * 4) * 4;
            CP_ASYNC16(d, src);
            CP_ASYNC16(d + 64 * TW * 4, src + (size_t)64 * K);
        }
        CP_COMMIT();
        CP_WAIT0();
        __syncthreads();

        const uint32_t* As  = sm + 0 * TILE_W;
        const uint32_t* Als = sm + 1 * TILE_W;
        const uint32_t* Bs  = sm + 2 * TILE_W;
        const uint32_t* Bls = sm + 3 * TILE_W;

        #pragma unroll
        for (int kk = 0; kk < 2; kk++) {
            const int kw = kk * 8;
            uint32_t ah[4][4], al[4][4], bh[4][2], bl[4][2];
            #pragma unroll
            for (int mf = 0; mf < 4; mf++) {
                const int m0 = wm * 64 + mf * 16;
                const int i0 = (m0 + g) * TW + t + kw;
                const int i8 = (m0 + g + 8) * TW + t + kw;
                ah[mf][0] = As[i0];  ah[mf][1] = As[i8];
                ah[mf][2] = As[i0 + 4]; ah[mf][3] = As[i8 + 4];
                al[mf][0] = Als[i0]; al[mf][1] = Als[i8];
                al[mf][2] = Als[i0 + 4]; al[mf][3] = Als[i8 + 4];
            }
            #pragma unroll
            for (int nf = 0; nf < 4; nf++) {
                const int n0 = wn * 32 + nf * 8;
                const int j0 = (n0 + g) * TW + t + kw;
                bh[nf][0] = Bs[j0];  bh[nf][1] = Bs[j0 + 4];
                bl[nf][0] = Bls[j0]; bl[nf][1] = Bls[j0 + 4];
            }
            #pragma unroll
            for (int mf = 0; mf < 4; mf++)
                #pragma unroll
                for (int nf = 0; nf < 4; nf++) {
                    mma16816(acc[mf][nf], ah[mf], bh[nf]);
                    mma16816(acc[mf][nf], ah[mf], bl[nf]);
                    mma16816(acc[mf][nf], al[mf], bh[nf]);
                }
        }
        __syncthreads();
    }

    #pragma unroll
    for (int mf = 0; mf < 4; mf++) {
        const int m = bm + wm * 64 + mf * 16 + g;
        #pragma unroll
        for (int nf = 0; nf < 4; nf++) {
            const int n = bn + wn * 32 + nf * 8 + 2 * t;
            float v0 = acc[mf][nf][0] * scale, v1 = acc[mf][nf][1] * scale;
            float v2 = acc[mf][nf][2] * scale, v3 = acc[mf][nf][3] * scale;
            if (Cf) {
                *(float2*)(Cf + (size_t)m * N + n)       = make_float2(v0, v1);
                *(float2*)(Cf + (size_t)(m + 8) * N + n) = make_float2(v2, v3);
            }
            if (H1 && H2) {           // fp16 2-term split output
                uint32_t h01, l01, h23, l23;
                split_pack2h(v0, v1, h01, l01);
                split_pack2h(v2, v3, h23, l23);
                *(uint32_t*)(H1 + (size_t)m * N + n)       = h01;
                *(uint32_t*)(H2 + (size_t)m * N + n)       = l01;
                *(uint32_t*)(H1 + (size_t)(m + 8) * N + n) = h23;
                *(uint32_t*)(H2 + (size_t)(m + 8) * N + n) = l23;
            } else if (H1) {          // fp16 single output
                *(uint32_t*)(H1 + (size_t)m * N + n)       = packh2(v0, v1);
                *(uint32_t*)(H1 + (size_t)(m + 8) * N + n) = packh2(v2, v3);
            }
        }
    }
}

// Batched Q/K/V projection GEMM: grid.z selects tensor set via global symbols.
__global__ __launch_bounds__(256) void gemm_qkv(int M, int N, int K) {
    __shared__ uint32_t sm[4 * TILE_W];
    switch (blockIdx.z) {
        case 0:  gemm_core(g_qh, g_ql, g_wqh, g_wql, nullptr, g_qph, g_qpl,
                           0.125f, M, N, K, sm); break;
        case 1:  gemm_core(g_kh, g_kl, g_wkh, g_wkl, nullptr, g_kp, nullptr,
                           1.0f, M, N, K, sm); break;
        default: gemm_core(g_vh, g_vl, g_wvh, g_wvl, nullptr, g_vph, g_vpl,
                           1.0f, M, N, K, sm); break;
    }
}

__global__ __launch_bounds__(256) void gemm_wo(float* __restrict__ Cf,
                                               int M, int N, int K) {
    __shared__ uint32_t sm[4 * TILE_W];
    // bf16 3-term path with bf16 split inputs (attn output), fp32 out
    const int tid = threadIdx.x;
    (void)tid;
    gemm_core(g_ch, g_cl, g_woh, g_wol, Cf, nullptr, nullptr, 1.0f, M, N, K, sm);
}

// ---------------------------------------------------------------------------
// Flash attention: 128 queries/block, 8 warps, KV tile = 32, single-buffered.
// QK^T: fp16, Q 2-term + K single (2 MMAs). PV: fp16, P single + V 2-term
// (2 MMAs). SMEM: K 4608 + V 10240 = 14848 B static.
// ---------------------------------------------------------------------------
#define FKP 72
#define FVP 40

__global__ __launch_bounds__(256) void flash_mma() {
    __shared__ __half Ksh[32 * FKP];
    __shared__ __half Vsh[64 * FVP], Vsl[64 * FVP];

    const int tid = threadIdx.x, wid = tid >> 5, lane = tid & 31;
    const int g = lane >> 2, t = lane & 3;
    const int qt = blockIdx.x, h = blockIdx.y, b = blockIdx.z;
    const int q0 = qt * 128, m0 = wid * 16;

    uint32_t qhf[4][4], qlf[4][4];
    {
        const size_t rbase = (size_t)(b * SEQ + q0 + m0 + g) * EMB + h * HD;
        const __half* q0h = g_qph + rbase;
        const __half* q8h = q0h + (size_t)8 * EMB;
        const __half* q0l = g_qpl + rbase;
        const __half* q8l = q0l + (size_t)8 * EMB;
        #pragma unroll
        for (int kc = 0; kc < 4; kc++) {
            const int d0 = kc * 16 + 2 * t;
            qhf[kc][0] = *(const uint32_t*)(q0h + d0);
            qhf[kc][1] = *(const uint32_t*)(q8h + d0);
            qhf[kc][2] = *(const uint32_t*)(q0h + d0 + 8);
            qhf[kc][3] = *(const uint32_t*)(q8h + d0 + 8);
            qlf[kc][0] = *(const uint32_t*)(q0l + d0);
            qlf[kc][1] = *(const uint32_t*)(q8l + d0);
            qlf[kc][2] = *(const uint32_t*)(q0l + d0 + 8);
            qlf[kc][3] = *(const uint32_t*)(q8l + d0 + 8);
        }
    }

    float O[8][4] = {};
    float m_g = -1e30f, m_g8 = -1e30f, l_g = 0.f, l_g8 = 0.f;

    const int kr = tid >> 3, kc8 = tid & 7;   // K loader: 32 rows x 8 chunks, 1/thread
    const int vd = tid >> 2, vc = tid & 3;    // V loader: 64 rows x 4 chunks x 2 arrays
    const __half* khb = g_kp + (size_t)(b * SEQ) * EMB + h * HD;
    const __half* vhb = g_vth + (size_t)((b * NH + h) * HD) * SEQ;
    const __half* vlb = g_vtl + (size_t)((b * NH + h) * HD) * SEQ;
    const uint32_t sKh = smem_u32(Ksh);
    const uint32_t sVh = smem_u32(Vsh), sVl = smem_u32(Vsl);

    for (int j0 = 0; j0 < SEQ; j0 += 32) {
        {
            const __half* ks = khb + (size_t)(j0 + kr) * EMB + kc8 * 8;
            CP_ASYNC16(sKh + kr * (FKP * 2) + kc8 * 16, ks);
            const __half* vs = vhb + (size_t)vd * SEQ + j0 + vc * 8;
            const __half* ws = vlb + (size_t)vd * SEQ + j0 + vc * 8;
            const uint32_t vdd = vd * (FVP * 2) + vc * 16;
            CP_ASYNC16(sVh + vdd, vs);
            CP_ASYNC16(sVl + vdd, ws);
        }
        CP_COMMIT();
        CP_WAIT0();
        __syncthreads();

        // S = Q K^T  (fp16: Qh·K + Ql·K)
        float s[4][4] = {};
        #pragma unroll
        for (int kc = 0; kc < 4; kc++) {
            uint32_t bk[4][2];
            #pragma unroll
            for (int nf = 0; nf < 4; nf++) {
                const int base = (nf * 8 + g) * FKP + kc * 16 + 2 * t;
                bk[nf][0] = *(const uint32_t*)(Ksh + base);
                bk[nf][1] = *(const uint32_t*)(Ksh + base + 8);
            }
            #pragma unroll
            for (int nf = 0; nf < 4; nf++) {
                mma16816h(s[nf], qhf[kc], bk[nf]);
                mma16816h(s[nf], qlf[kc], bk[nf]);
            }
        }

        // online softmax
        float mx0 = -1e30f, mx8 = -1e30f;
        #pragma unroll
        for (int nf = 0; nf < 4; nf++) {
            mx0 = fmaxf(mx0, fmaxf(s[nf][0], s[nf][1]));
            mx8 = fmaxf(mx8, fmaxf(s[nf][2], s[nf][3]));
        }
        mx0 = fmaxf(mx0, __shfl_xor_sync(0xffffffffu, mx0, 1));
        mx0 = fmaxf(mx0, __shfl_xor_sync(0xffffffffu, mx0, 2));
        mx8 = fmaxf(mx8, __shfl_xor_sync(0xffffffffu, mx8, 1));
        mx8 = fmaxf(mx8, __shfl_xor_sync(0xffffffffu, mx8, 2));
        const float mn_g = fmaxf(m_g, mx0), mn_g8 = fmaxf(m_g8, mx8);
        const float alpha_g = __expf(m_g - mn_g), alpha_g8 = __expf(m_g8 - mn_g8);
        m_g = mn_g; m_g8 = mn_g8;

        float p[4][4];
        float sum0 = 0.f, sum8 = 0.f;
        #pragma unroll
        for (int nf = 0; nf < 4; nf++) {
            p[nf][0] = __expf(s[nf][0] - mn_g);
            p[nf][1] = __expf(s[nf][1] - mn_g);
            p[nf][2] = __expf(s[nf][2] - mn_g8);
            p[nf][3] = __expf(s[nf][3] - mn_g8);
            sum0 += p[nf][0] + p[nf][1];
            sum8 += p[nf][2] + p[nf][3];
        }
        sum0 += __shfl_xor_sync(0xffffffffu, sum0, 1);
        sum0 += __shfl_xor_sync(0xffffffffu, sum0, 2);
        sum8 += __shfl_xor_sync(0xffffffffu, sum8, 1);
        sum8 += __shfl_xor_sync(0xffffffffu, sum8, 2);
        l_g  = l_g  * alpha_g  + sum0;
        l_g8 = l_g8 * alpha_g8 + sum8;

        #pragma unroll
        for (int nf2 = 0; nf2 < 8; nf2++) {
            O[nf2][0] *= alpha_g;  O[nf2][1] *= alpha_g;
            O[nf2][2] *= alpha_g8; O[nf2][3] *= alpha_g8;
        }

        // P fragments: fp16, no split
        uint32_t pf[2][4];
        #pragma unroll
        for (int kc2 = 0; kc2 < 2; kc2++) {
            const int nA = 2 * kc2, nB = 2 * kc2 + 1;
            pf[kc2][0] = packh2(p[nA][0], p[nA][1]);
            pf[kc2][1] = packh2(p[nA][2], p[nA][3]);
            pf[kc2][2] = packh2(p[nB][0], p[nB][1]);
            pf[kc2][3] = packh2(p[nB][2], p[nB][3]);
        }

        // O += P V  (fp16: 2 MMAs per tile)
        #pragma unroll
        for (int nf2 = 0; nf2 < 8; nf2++) {
            #pragma unroll
            for (int kc2 = 0; kc2 < 2; kc2++) {
                const int base = (nf2 * 8 + g) * FVP + kc2 * 16 + 2 * t;
                uint32_t vbh[2], vbl[2];
                vbh[0] = *(const uint32_t*)(Vsh + base);
                vbh[1] = *(const uint32_t*)(Vsh + base + 8);
                vbl[0] = *(const uint32_t*)(Vsl + base);
                vbl[1] = *(const uint32_t*)(Vsl + base + 8);
                mma16816h(O[nf2], pf[kc2], vbh);
                mma16816h(O[nf2], pf[kc2], vbl);
            }
        }
        __syncthreads();
    }

    const float li_g = 1.0f / l_g, li_g8 = 1.0f / l_g8;
    const size_t row0 = (size_t)(b * SEQ + q0 + m0 + g) * EMB;
    const size_t row8 = row0 + (size_t)8 * EMB;
    #pragma unroll
    for (int nf2 = 0; nf2 < 8; nf2++) {
        const int col = h * HD + nf2 * 8 + 2 * t;
        uint32_t h01, l01, h23, l23;
        split_pack2(O[nf2][0] * li_g,  O[nf2][1] * li_g,  h01, l01);
        split_pack2(O[nf2][2] * li_g8, O[nf2][3] * li_g8, h23, l23);
        *(uint32_t*)(g_ch + row0 + col) = h01;
        *(uint32_t*)(g_cl + row0 + col) = l01;
        *(uint32_t*)(g_ch + row8 + col) = h23;
        *(uint32_t*)(g_cl + row8 + col) = l23;
    }
}

// ---------------------------------------------------------------------------
extern "C" void kernel_launch(void* const* d_in, const int* in_sizes, int n_in,
                              void* d_out, int out_size)
{
    const float* Q  = (const float*)d_in[0];
    const float* K  = (const float*)d_in[1];
    const float* V  = (const float*)d_in[2];
    const float* Wq = (const float*)d_in[3];
    const float* Wk = (const float*)d_in[4];
    const float* Wv = (const float*)d_in[5];
    const float* Wo = (const float*)d_in[6];
    float* out = (float*)d_out;

    const int n4 = MROWS * EMB / 4;
    const int sb = 256, sg = (n4 + sb - 1) / sb;
    split_bf16_3<<<dim3(sg, 3), sb>>>(Q, K, V, n4);

    dim3 tb(32, 8);
    transpose_split_4<<<dim3(EMB / 32, EMB / 32, 4), tb>>>(Wq, Wk, Wv, Wo);

    gemm_qkv<<<dim3(EMB / 128, MROWS / 128, 3), 256>>>(MROWS, EMB, EMB);

    dim3 vt(SEQ / 32, HD / 32, BATCH * NH);    // (64, 2, 32)
    transpose_v<<<vt, tb>>>();

    dim3 ga(SEQ / 128, NH, BATCH);             // (16, 16, 2)
    flash_mma<<<ga, 256>>>();

    gemm_wo<<<dim3(EMB / 128, MROWS / 128), 256>>>(out, MROWS, EMB, EMB);
}

// round 14
// speedup vs baseline: 1.5429x; 1.1709x over previous
#include <cuda_runtime.h>
#include <cuda_bf16.h>
#include <cuda_fp16.h>
#include <cstdint>
#include <cstring>

#define BATCH 2
#define SEQ   2048
#define EMB   1024
#define NH    16
#define HD    64
#define MROWS (BATCH*SEQ)   // 4096

// ---------------------------------------------------------------------------
// Scratch (static device globals). All kernels reference symbols directly.
// ---------------------------------------------------------------------------
__device__ __half g_qh[MROWS * EMB], g_ql[MROWS * EMB];      // input splits, fp16 2-term
__device__ __half g_kh[MROWS * EMB], g_kl[MROWS * EMB];
__device__ __half g_vh[MROWS * EMB], g_vl[MROWS * EMB];
__device__ __half g_qph[MROWS * EMB], g_qpl[MROWS * EMB];    // Q proj, fp16 2-term, pre-scaled
__device__ __half g_kp [MROWS * EMB];                         // K proj, fp16 single
__device__ __half g_vph[MROWS * EMB], g_vpl[MROWS * EMB];    // V proj, fp16 2-term
__device__ __half g_vth[MROWS * EMB], g_vtl[MROWS * EMB];    // fp16 V^T hi/lo
__device__ __half g_ch[MROWS * EMB], g_cl[MROWS * EMB];      // attn out, fp16 2-term
__device__ __half g_wq16[EMB * EMB], g_wk16[EMB * EMB];      // weights, fp16 single, [N][K]
__device__ __half g_wv16[EMB * EMB], g_wo16[EMB * EMB];

// ---------------------------------------------------------------------------
// Helpers
// ---------------------------------------------------------------------------
__device__ __forceinline__ uint32_t smem_u32(const void* p) {
    uint32_t a;
    asm("{ .reg .u64 t; cvta.to.shared.u64 t, %1; cvt.u32.u64 %0, t; }" : "=r"(a) : "l"(p));
    return a;
}

#define CP_ASYNC16(dst, src) \
    asm volatile("cp.async.cg.shared.global [%0], [%1], 16;" :: "r"((uint32_t)(dst)), "l"(src))
#define CP_COMMIT() asm volatile("cp.async.commit_group;" ::: "memory")
#define CP_WAIT0()  asm volatile("cp.async.wait_group 0;" ::: "memory")

// mma.sync m16n8k16 fp16 -> f32
__device__ __forceinline__ void mma16816h(float* c, const uint32_t* a, const uint32_t* b) {
    asm volatile(
        "mma.sync.aligned.m16n8k16.row.col.f32.f16.f16.f32 "
        "{%0,%1,%2,%3}, {%4,%5,%6,%7}, {%8,%9}, {%0,%1,%2,%3};"
        : "+f"(c[0]), "+f"(c[1]), "+f"(c[2]), "+f"(c[3])
        : "r"(a[0]), "r"(a[1]), "r"(a[2]), "r"(a[3]), "r"(b[0]), "r"(b[1]));
}

__device__ __forceinline__ uint32_t packh2(float x0, float x1) {
    __half2 h = __float22half2_rn(make_float2(x0, x1));
    uint32_t u;
    memcpy(&u, &h, 4);
    return u;
}
// fp16 2-term split of a float pair, packed
__device__ __forceinline__ void split_pack2h(float x0, float x1, uint32_t& hi, uint32_t& lo) {
    __half h0 = __float2half_rn(x0), h1 = __float2half_rn(x1);
    float l0 = x0 - __half2float(h0), l1 = x1 - __half2float(h1);
    __half2 hh = __halves2half2(h0, h1);
    __half2 ll = __floats2half2_rn(l0, l1);
    memcpy(&hi, &hh, 4);
    memcpy(&lo, &ll, 4);
}

// ---------------------------------------------------------------------------
// Pre-pass 1: batched fp16 hi/lo split of Q,K,V (grid.y in {0,1,2})
// ---------------------------------------------------------------------------
__global__ void split_h16_3(const float* __restrict__ Q, const float* __restrict__ K,
                            const float* __restrict__ V, int n4) {
    const int z = blockIdx.y;
    int i = blockIdx.x * blockDim.x + threadIdx.x;
    if (i >= n4) return;
    const float* x;
    __half *hi, *lo;
    switch (z) {
        case 0:  x = Q; hi = g_qh; lo = g_ql; break;
        case 1:  x = K; hi = g_kh; lo = g_kl; break;
        default: x = V; hi = g_vh; lo = g_vl; break;
    }
    float4 v = ((const float4*)x)[i];
    uint32_t h01, l01, h23, l23;
    split_pack2h(v.x, v.y, h01, l01);
    split_pack2h(v.z, v.w, h23, l23);
    ((uint2*)hi)[i] = make_uint2(h01, h23);
    ((uint2*)lo)[i] = make_uint2(l01, l23);
}

// ---------------------------------------------------------------------------
// Pre-pass 2: batched W[K][N] -> Wt fp16 single [N][K] (grid.z in {0..3})
// ---------------------------------------------------------------------------
__global__ void transpose_w_4(const float* __restrict__ Wq, const float* __restrict__ Wk,
                              const float* __restrict__ Wv, const float* __restrict__ Wo) {
    __shared__ float t[32][33];
    const float* W;
    __half* T;
    switch (blockIdx.z) {
        case 0:  W = Wq; T = g_wq16; break;
        case 1:  W = Wk; T = g_wk16; break;
        case 2:  W = Wv; T = g_wv16; break;
        default: W = Wo; T = g_wo16; break;
    }
    int x = blockIdx.x * 32 + threadIdx.x;
    int y = blockIdx.y * 32 + threadIdx.y;
    #pragma unroll
    for (int i = 0; i < 32; i += 8)
        t[threadIdx.y + i][threadIdx.x] = W[(size_t)(y + i) * EMB + x];
    __syncthreads();
    int nx = blockIdx.y * 32 + threadIdx.x;
    int ny = blockIdx.x * 32 + threadIdx.y;
    #pragma unroll
    for (int i = 0; i < 32; i += 8)
        T[(size_t)(ny + i) * EMB + nx] = __float2half_rn(t[threadIdx.x][threadIdx.y + i]);
}

// ---------------------------------------------------------------------------
// V transpose: recombine fp16 hi/lo -> float -> fp16 hi/lo, transposed
// ---------------------------------------------------------------------------
__global__ void transpose_v() {
    __shared__ float a[32][33];
    const int bh = blockIdx.z;
    const int b = bh >> 4, h = bh & 15;
    const int s0 = blockIdx.x * 32, d0 = blockIdx.y * 32;
    const int tx = threadIdx.x, ty = threadIdx.y;
    #pragma unroll
    for (int i = 0; i < 32; i += 8) {
        size_t src = (size_t)(b * SEQ + s0 + ty + i) * EMB + h * HD + d0 + tx;
        a[ty + i][tx] = __half2float(g_vph[src]) + __half2float(g_vpl[src]);
    }
    __syncthreads();
    #pragma unroll
    for (int i = 0; i < 32; i += 8) {
        size_t dst = (size_t)(bh * HD + d0 + ty + i) * SEQ + s0 + tx;
        float v = a[tx][ty + i];
        __half hh = __float2half_rn(v);
        g_vth[dst] = hh;
        g_vtl[dst] = __float2half_rn(v - __half2float(hh));
    }
}

// ---------------------------------------------------------------------------
// mma.sync 2x-fp16 GEMM core: C = (Ah+Al)[M,K] @ W16[N,K]^T.
// Block 128x128, BK=32, 256 threads, 8 warps 2x4, warp tile 64x32.
// SMEM: 3 tiles x 128 rows x 20 words = 30720 B static (in caller).
// Epilogue variants: fp32 (Cf), fp16 split (H1+H2), fp16 single (H1 only).
// ---------------------------------------------------------------------------
#define TW 20
#define TILE_W (128 * TW)

__device__ __forceinline__ void gemm_core_h(
    const __half* __restrict__ Ahi, const __half* __restrict__ Alo,
    const __half* __restrict__ B16,
    float* __restrict__ Cf, __half* __restrict__ H1, __half* __restrict__ H2,
    float scale, int M, int N, int K, uint32_t* sm)
{
    const int tid = threadIdx.x;
    const int wid = tid >> 5, lane = tid & 31;
    const int g = lane >> 2, t = lane & 3;
    const int wm = wid & 1, wn = wid >> 1;
    const int bm = blockIdx.y * 128, bn = blockIdx.x * 128;

    const uint32_t sbase = smem_u32(sm);
    const int r0 = tid >> 2, c0 = tid & 3;
    const __half* gsrc[3] = {
        Ahi + (size_t)bm * K, Alo + (size_t)bm * K, B16 + (size_t)bn * K
    };

    float acc[4][4][4] = {};

    const int NS = K / 32;
    for (int s = 0; s < NS; s++) {
        const int k0 = s * 32;
        #pragma unroll
        for (int tile = 0; tile < 3; tile++) {
            const __half* src = gsrc[tile] + (size_t)r0 * K + k0 + c0 * 8;
            uint32_t d = sbase + (tile * TILE_W + r0 * TW + c0 * 4) * 4;
            CP_ASYNC16(d, src);
            CP_ASYNC16(d + 64 * TW * 4, src + (size_t)64 * K);
        }
        CP_COMMIT();
        CP_WAIT0();
        __syncthreads();

        const uint32_t* As  = sm + 0 * TILE_W;
        const uint32_t* Als = sm + 1 * TILE_W;
        const uint32_t* Bs  = sm + 2 * TILE_W;

        #pragma unroll
        for (int kk = 0; kk < 2; kk++) {
            const int kw = kk * 8;
            uint32_t ah[4][4], al[4][4], bb[4][2];
            #pragma unroll
            for (int mf = 0; mf < 4; mf++) {
                const int m0 = wm * 64 + mf * 16;
                const int i0 = (m0 + g) * TW + t + kw;
                const int i8 = (m0 + g + 8) * TW + t + kw;
                ah[mf][0] = As[i0];  ah[mf][1] = As[i8];
                ah[mf][2] = As[i0 + 4]; ah[mf][3] = As[i8 + 4];
                al[mf][0] = Als[i0]; al[mf][1] = Als[i8];
                al[mf][2] = Als[i0 + 4]; al[mf][3] = Als[i8 + 4];
            }
            #pragma unroll
            for (int nf = 0; nf < 4; nf++) {
                const int n0 = wn * 32 + nf * 8;
                const int j0 = (n0 + g) * TW + t + kw;
                bb[nf][0] = Bs[j0];  bb[nf][1] = Bs[j0 + 4];
            }
            #pragma unroll
            for (int mf = 0; mf < 4; mf++)
                #pragma unroll
                for (int nf = 0; nf < 4; nf++) {
                    mma16816h(acc[mf][nf], ah[mf], bb[nf]);
                    mma16816h(acc[mf][nf], al[mf], bb[nf]);
                }
        }
        __syncthreads();
    }

    #pragma unroll
    for (int mf = 0; mf < 4; mf++) {
        const int m = bm + wm * 64 + mf * 16 + g;
        #pragma unroll
        for (int nf = 0; nf < 4; nf++) {
            const int n = bn + wn * 32 + nf * 8 + 2 * t;
            float v0 = acc[mf][nf][0] * scale, v1 = acc[mf][nf][1] * scale;
            float v2 = acc[mf][nf][2] * scale, v3 = acc[mf][nf][3] * scale;
            if (Cf) {
                *(float2*)(Cf + (size_t)m * N + n)       = make_float2(v0, v1);
                *(float2*)(Cf + (size_t)(m + 8) * N + n) = make_float2(v2, v3);
            }
            if (H1 && H2) {
                uint32_t h01, l01, h23, l23;
                split_pack2h(v0, v1, h01, l01);
                split_pack2h(v2, v3, h23, l23);
                *(uint32_t*)(H1 + (size_t)m * N + n)       = h01;
                *(uint32_t*)(H2 + (size_t)m * N + n)       = l01;
                *(uint32_t*)(H1 + (size_t)(m + 8) * N + n) = h23;
                *(uint32_t*)(H2 + (size_t)(m + 8) * N + n) = l23;
            } else if (H1) {
                *(uint32_t*)(H1 + (size_t)m * N + n)       = packh2(v0, v1);
                *(uint32_t*)(H1 + (size_t)(m + 8) * N + n) = packh2(v2, v3);
            }
        }
    }
}

// Batched Q/K/V projection GEMM: grid.z selects tensor set via global symbols.
__global__ __launch_bounds__(256) void gemm_qkv(int M, int N, int K) {
    __shared__ uint32_t sm[3 * TILE_W];
    switch (blockIdx.z) {
        case 0:  gemm_core_h(g_qh, g_ql, g_wq16, nullptr, g_qph, g_qpl,
                             0.125f, M, N, K, sm); break;
        case 1:  gemm_core_h(g_kh, g_kl, g_wk16, nullptr, g_kp, nullptr,
                             1.0f, M, N, K, sm); break;
        default: gemm_core_h(g_vh, g_vl, g_wv16, nullptr, g_vph, g_vpl,
                             1.0f, M, N, K, sm); break;
    }
}

__global__ __launch_bounds__(256) void gemm_wo(float* __restrict__ Cf,
                                               int M, int N, int K) {
    __shared__ uint32_t sm[3 * TILE_W];
    gemm_core_h(g_ch, g_cl, g_wo16, Cf, nullptr, nullptr, 1.0f, M, N, K, sm);
}

// ---------------------------------------------------------------------------
// Flash attention: 128 queries/block, 8 warps, KV tile = 32, single-buffered.
// QK^T: fp16, Q 2-term + K single (2 MMAs). PV: fp16, P single + V 2-term
// (2 MMAs). SMEM: K 4608 + V 10240 = 14848 B static.
// ---------------------------------------------------------------------------
#define FKP 72
#define FVP 40

__global__ __launch_bounds__(256) void flash_mma() {
    __shared__ __half Ksh[32 * FKP];
    __shared__ __half Vsh[64 * FVP], Vsl[64 * FVP];

    const int tid = threadIdx.x, wid = tid >> 5, lane = tid & 31;
    const int g = lane >> 2, t = lane & 3;
    const int qt = blockIdx.x, h = blockIdx.y, b = blockIdx.z;
    const int q0 = qt * 128, m0 = wid * 16;

    uint32_t qhf[4][4], qlf[4][4];
    {
        const size_t rbase = (size_t)(b * SEQ + q0 + m0 + g) * EMB + h * HD;
        const __half* q0h = g_qph + rbase;
        const __half* q8h = q0h + (size_t)8 * EMB;
        const __half* q0l = g_qpl + rbase;
        const __half* q8l = q0l + (size_t)8 * EMB;
        #pragma unroll
        for (int kc = 0; kc < 4; kc++) {
            const int d0 = kc * 16 + 2 * t;
            qhf[kc][0] = *(const uint32_t*)(q0h + d0);
            qhf[kc][1] = *(const uint32_t*)(q8h + d0);
            qhf[kc][2] = *(const uint32_t*)(q0h + d0 + 8);
            qhf[kc][3] = *(const uint32_t*)(q8h + d0 + 8);
            qlf[kc][0] = *(const uint32_t*)(q0l + d0);
            qlf[kc][1] = *(const uint32_t*)(q8l + d0);
            qlf[kc][2] = *(const uint32_t*)(q0l + d0 + 8);
            qlf[kc][3] = *(const uint32_t*)(q8l + d0 + 8);
        }
    }

    float O[8][4] = {};
    float m_g = -1e30f, m_g8 = -1e30f, l_g = 0.f, l_g8 = 0.f;

    const int kr = tid >> 3, kc8 = tid & 7;
    const int vd = tid >> 2, vc = tid & 3;
    const __half* khb = g_kp + (size_t)(b * SEQ) * EMB + h * HD;
    const __half* vhb = g_vth + (size_t)((b * NH + h) * HD) * SEQ;
    const __half* vlb = g_vtl + (size_t)((b * NH + h) * HD) * SEQ;
    const uint32_t sKh = smem_u32(Ksh);
    const uint32_t sVh = smem_u32(Vsh), sVl = smem_u32(Vsl);

    for (int j0 = 0; j0 < SEQ; j0 += 32) {
        {
            const __half* ks = khb + (size_t)(j0 + kr) * EMB + kc8 * 8;
            CP_ASYNC16(sKh + kr * (FKP * 2) + kc8 * 16, ks);
            const __half* vs = vhb + (size_t)vd * SEQ + j0 + vc * 8;
            const __half* ws = vlb + (size_t)vd * SEQ + j0 + vc * 8;
            const uint32_t vdd = vd * (FVP * 2) + vc * 16;
            CP_ASYNC16(sVh + vdd, vs);
            CP_ASYNC16(sVl + vdd, ws);
        }
        CP_COMMIT();
        CP_WAIT0();
        __syncthreads();

        // S = Q K^T  (fp16: Qh·K + Ql·K)
        float s[4][4] = {};
        #pragma unroll
        for (int kc = 0; kc < 4; kc++) {
            uint32_t bk[4][2];
            #pragma unroll
            for (int nf = 0; nf < 4; nf++) {
                const int base = (nf * 8 + g) * FKP + kc * 16 + 2 * t;
                bk[nf][0] = *(const uint32_t*)(Ksh + base);
                bk[nf][1] = *(const uint32_t*)(Ksh + base + 8);
            }
            #pragma unroll
            for (int nf = 0; nf < 4; nf++) {
                mma16816h(s[nf], qhf[kc], bk[nf]);
                mma16816h(s[nf], qlf[kc], bk[nf]);
            }
        }

        // online softmax
        float mx0 = -1e30f, mx8 = -1e30f;
        #pragma unroll
        for (int nf = 0; nf < 4; nf++) {
            mx0 = fmaxf(mx0, fmaxf(s[nf][0], s[nf][1]));
            mx8 = fmaxf(mx8, fmaxf(s[nf][2], s[nf][3]));
        }
        mx0 = fmaxf(mx0, __shfl_xor_sync(0xffffffffu, mx0, 1));
        mx0 = fmaxf(mx0, __shfl_xor_sync(0xffffffffu, mx0, 2));
        mx8 = fmaxf(mx8, __shfl_xor_sync(0xffffffffu, mx8, 1));
        mx8 = fmaxf(mx8, __shfl_xor_sync(0xffffffffu, mx8, 2));
        const float mn_g = fmaxf(m_g, mx0), mn_g8 = fmaxf(m_g8, mx8);
        const float alpha_g = __expf(m_g - mn_g), alpha_g8 = __expf(m_g8 - mn_g8);
        m_g = mn_g; m_g8 = mn_g8;

        float p[4][4];
        float sum0 = 0.f, sum8 = 0.f;
        #pragma unroll
        for (int nf = 0; nf < 4; nf++) {
            p[nf][0] = __expf(s[nf][0] - mn_g);
            p[nf][1] = __expf(s[nf][1] - mn_g);
            p[nf][2] = __expf(s[nf][2] - mn_g8);
            p[nf][3] = __expf(s[nf][3] - mn_g8);
            sum0 += p[nf][0] + p[nf][1];
            sum8 += p[nf][2] + p[nf][3];
        }
        sum0 += __shfl_xor_sync(0xffffffffu, sum0, 1);
        sum0 += __shfl_xor_sync(0xffffffffu, sum0, 2);
        sum8 += __shfl_xor_sync(0xffffffffu, sum8, 1);
        sum8 += __shfl_xor_sync(0xffffffffu, sum8, 2);
        l_g  = l_g  * alpha_g  + sum0;
        l_g8 = l_g8 * alpha_g8 + sum8;

        #pragma unroll
        for (int nf2 = 0; nf2 < 8; nf2++) {
            O[nf2][0] *= alpha_g;  O[nf2][1] *= alpha_g;
            O[nf2][2] *= alpha_g8; O[nf2][3] *= alpha_g8;
        }

        // P fragments: fp16, no split
        uint32_t pf[2][4];
        #pragma unroll
        for (int kc2 = 0; kc2 < 2; kc2++) {
            const int nA = 2 * kc2, nB = 2 * kc2 + 1;
            pf[kc2][0] = packh2(p[nA][0], p[nA][1]);
            pf[kc2][1] = packh2(p[nA][2], p[nA][3]);
            pf[kc2][2] = packh2(p[nB][0], p[nB][1]);
            pf[kc2][3] = packh2(p[nB][2], p[nB][3]);
        }

        // O += P V  (fp16: 2 MMAs per tile)
        #pragma unroll
        for (int nf2 = 0; nf2 < 8; nf2++) {
            #pragma unroll
            for (int kc2 = 0; kc2 < 2; kc2++) {
                const int base = (nf2 * 8 + g) * FVP + kc2 * 16 + 2 * t;
                uint32_t vbh[2], vbl[2];
                vbh[0] = *(const uint32_t*)(Vsh + base);
                vbh[1] = *(const uint32_t*)(Vsh + base + 8);
                vbl[0] = *(const uint32_t*)(Vsl + base);
                vbl[1] = *(const uint32_t*)(Vsl + base + 8);
                mma16816h(O[nf2], pf[kc2], vbh);
                mma16816h(O[nf2], pf[kc2], vbl);
            }
        }
        __syncthreads();
    }

    const float li_g = 1.0f / l_g, li_g8 = 1.0f / l_g8;
    const size_t row0 = (size_t)(b * SEQ + q0 + m0 + g) * EMB;
    const size_t row8 = row0 + (size_t)8 * EMB;
    #pragma unroll
    for (int nf2 = 0; nf2 < 8; nf2++) {
        const int col = h * HD + nf2 * 8 + 2 * t;
        uint32_t h01, l01, h23, l23;
        split_pack2h(O[nf2][0] * li_g,  O[nf2][1] * li_g,  h01, l01);
        split_pack2h(O[nf2][2] * li_g8, O[nf2][3] * li_g8, h23, l23);
        *(uint32_t*)(g_ch + row0 + col) = h01;
        *(uint32_t*)(g_cl + row0 + col) = l01;
        *(uint32_t*)(g_ch + row8 + col) = h23;
        *(uint32_t*)(g_cl + row8 + col) = l23;
    }
}

// ---------------------------------------------------------------------------
extern "C" void kernel_launch(void* const* d_in, const int* in_sizes, int n_in,
                              void* d_out, int out_size)
{
    const float* Q  = (const float*)d_in[0];
    const float* K  = (const float*)d_in[1];
    const float* V  = (const float*)d_in[2];
    const float* Wq = (const float*)d_in[3];
    const float* Wk = (const float*)d_in[4];
    const float* Wv = (const float*)d_in[5];
    const float* Wo = (const float*)d_in[6];
    float* out = (float*)d_out;

    const int n4 = MROWS * EMB / 4;
    const int sb = 256, sg = (n4 + sb - 1) / sb;
    split_h16_3<<<dim3(sg, 3), sb>>>(Q, K, V, n4);

    dim3 tb(32, 8);
    transpose_w_4<<<dim3(EMB / 32, EMB / 32, 4), tb>>>(Wq, Wk, Wv, Wo);

    gemm_qkv<<<dim3(EMB / 128, MROWS / 128, 3), 256>>>(MROWS, EMB, EMB);

    dim3 vt(SEQ / 32, HD / 32, BATCH * NH);    // (64, 2, 32)
    transpose_v<<<vt, tb>>>();

    dim3 ga(SEQ / 128, NH, BATCH);             // (16, 16, 2)
    flash_mma<<<ga, 256>>>();

    gemm_wo<<<dim3(EMB / 128, MROWS / 128), 256>>>(out, MROWS, EMB, EMB);
}

// round 15
// speedup vs baseline: 1.8273x; 1.1843x over previous
#include <cuda_runtime.h>
#include <cuda_bf16.h>
#include <cuda_fp16.h>
#include <cstdint>
#include <cstring>

#define BATCH 2
#define SEQ   2048
#define EMB   1024
#define NH    16
#define HD    64
#define MROWS (BATCH*SEQ)   // 4096

// ---------------------------------------------------------------------------
// Scratch (static device globals). All kernels reference symbols directly.
// ---------------------------------------------------------------------------
__device__ __half g_qh[MROWS * EMB], g_ql[MROWS * EMB];      // input splits, fp16 2-term
__device__ __half g_kh[MROWS * EMB], g_kl[MROWS * EMB];
__device__ __half g_vh[MROWS * EMB], g_vl[MROWS * EMB];
__device__ __half g_qp [MROWS * EMB];                         // Q proj, fp16 single, pre-scaled
__device__ __half g_kp [MROWS * EMB];                         // K proj, fp16 single
__device__ __half g_vp [MROWS * EMB];                         // V proj, fp16 single
__device__ __half g_vt [MROWS * EMB];                         // fp16 V^T
__device__ __half g_ch[MROWS * EMB], g_cl[MROWS * EMB];      // attn out, fp16 2-term
__device__ __half g_wq16[EMB * EMB], g_wk16[EMB * EMB];      // weights, fp16 single, [N][K]
__device__ __half g_wv16[EMB * EMB], g_wo16[EMB * EMB];

// ---------------------------------------------------------------------------
// Helpers
// ---------------------------------------------------------------------------
__device__ __forceinline__ uint32_t smem_u32(const void* p) {
    uint32_t a;
    asm("{ .reg .u64 t; cvta.to.shared.u64 t, %1; cvt.u32.u64 %0, t; }" : "=r"(a) : "l"(p));
    return a;
}

#define CP_ASYNC16(dst, src) \
    asm volatile("cp.async.cg.shared.global [%0], [%1], 16;" :: "r"((uint32_t)(dst)), "l"(src))
#define CP_COMMIT() asm volatile("cp.async.commit_group;" ::: "memory")
#define CP_WAIT0()  asm volatile("cp.async.wait_group 0;" ::: "memory")

// mma.sync m16n8k16 fp16 -> f32
__device__ __forceinline__ void mma16816h(float* c, const uint32_t* a, const uint32_t* b) {
    asm volatile(
        "mma.sync.aligned.m16n8k16.row.col.f32.f16.f16.f32 "
        "{%0,%1,%2,%3}, {%4,%5,%6,%7}, {%8,%9}, {%0,%1,%2,%3};"
        : "+f"(c[0]), "+f"(c[1]), "+f"(c[2]), "+f"(c[3])
        : "r"(a[0]), "r"(a[1]), "r"(a[2]), "r"(a[3]), "r"(b[0]), "r"(b[1]));
}

__device__ __forceinline__ uint32_t packh2(float x0, float x1) {
    __half2 h = __float22half2_rn(make_float2(x0, x1));
    uint32_t u;
    memcpy(&u, &h, 4);
    return u;
}
// fp16 2-term split of a float pair, packed
__device__ __forceinline__ void split_pack2h(float x0, float x1, uint32_t& hi, uint32_t& lo) {
    __half h0 = __float2half_rn(x0), h1 = __float2half_rn(x1);
    float l0 = x0 - __half2float(h0), l1 = x1 - __half2float(h1);
    __half2 hh = __halves2half2(h0, h1);
    __half2 ll = __floats2half2_rn(l0, l1);
    memcpy(&hi, &hh, 4);
    memcpy(&lo, &ll, 4);
}

// ---------------------------------------------------------------------------
// Pre-pass 1: batched fp16 hi/lo split of Q,K,V (grid.y in {0,1,2})
// ---------------------------------------------------------------------------
__global__ void split_h16_3(const float* __restrict__ Q, const float* __restrict__ K,
                            const float* __restrict__ V, int n4) {
    const int z = blockIdx.y;
    int i = blockIdx.x * blockDim.x + threadIdx.x;
    if (i >= n4) return;
    const float* x;
    __half *hi, *lo;
    switch (z) {
        case 0:  x = Q; hi = g_qh; lo = g_ql; break;
        case 1:  x = K; hi = g_kh; lo = g_kl; break;
        default: x = V; hi = g_vh; lo = g_vl; break;
    }
    float4 v = ((const float4*)x)[i];
    uint32_t h01, l01, h23, l23;
    split_pack2h(v.x, v.y, h01, l01);
    split_pack2h(v.z, v.w, h23, l23);
    ((uint2*)hi)[i] = make_uint2(h01, h23);
    ((uint2*)lo)[i] = make_uint2(l01, l23);
}

// ---------------------------------------------------------------------------
// Pre-pass 2: batched W[K][N] -> Wt fp16 single [N][K] (grid.z in {0..3})
// ---------------------------------------------------------------------------
__global__ void transpose_w_4(const float* __restrict__ Wq, const float* __restrict__ Wk,
                              const float* __restrict__ Wv, const float* __restrict__ Wo) {
    __shared__ float t[32][33];
    const float* W;
    __half* T;
    switch (blockIdx.z) {
        case 0:  W = Wq; T = g_wq16; break;
        case 1:  W = Wk; T = g_wk16; break;
        case 2:  W = Wv; T = g_wv16; break;
        default: W = Wo; T = g_wo16; break;
    }
    int x = blockIdx.x * 32 + threadIdx.x;
    int y = blockIdx.y * 32 + threadIdx.y;
    #pragma unroll
    for (int i = 0; i < 32; i += 8)
        t[threadIdx.y + i][threadIdx.x] = W[(size_t)(y + i) * EMB + x];
    __syncthreads();
    int nx = blockIdx.y * 32 + threadIdx.x;
    int ny = blockIdx.x * 32 + threadIdx.y;
    #pragma unroll
    for (int i = 0; i < 32; i += 8)
        T[(size_t)(ny + i) * EMB + nx] = __float2half_rn(t[threadIdx.x][threadIdx.y + i]);
}

// ---------------------------------------------------------------------------
// V transpose (plain fp16): [b*S+s][h*64+d] -> [(b*16+h)*64+d][s]
// ---------------------------------------------------------------------------
__global__ void transpose_v() {
    __shared__ __half a[32][33];
    const int bh = blockIdx.z;
    const int b = bh >> 4, h = bh & 15;
    const int s0 = blockIdx.x * 32, d0 = blockIdx.y * 32;
    const int tx = threadIdx.x, ty = threadIdx.y;
    #pragma unroll
    for (int i = 0; i < 32; i += 8) {
        size_t src = (size_t)(b * SEQ + s0 + ty + i) * EMB + h * HD + d0 + tx;
        a[ty + i][tx] = g_vp[src];
    }
    __syncthreads();
    #pragma unroll
    for (int i = 0; i < 32; i += 8) {
        size_t dst = (size_t)(bh * HD + d0 + ty + i) * SEQ + s0 + tx;
        g_vt[dst] = a[tx][ty + i];
    }
}

// ---------------------------------------------------------------------------
// mma.sync 2x-fp16 GEMM core: C = (Ah+Al)[M,K] @ W16[N,K]^T.
// Block 128x128, BK=32, 256 threads, 8 warps 2x4, warp tile 64x32.
// SMEM: 3 tiles x 128 rows x 20 words = 30720 B static (in caller).
// Epilogue variants: fp32 (Cf), fp16 split (H1+H2), fp16 single (H1 only).
// ---------------------------------------------------------------------------
#define TW 20
#define TILE_W (128 * TW)

__device__ __forceinline__ void gemm_core_h(
    const __half* __restrict__ Ahi, const __half* __restrict__ Alo,
    const __half* __restrict__ B16,
    float* __restrict__ Cf, __half* __restrict__ H1, __half* __restrict__ H2,
    float scale, int M, int N, int K, uint32_t* sm)
{
    const int tid = threadIdx.x;
    const int wid = tid >> 5, lane = tid & 31;
    const int g = lane >> 2, t = lane & 3;
    const int wm = wid & 1, wn = wid >> 1;
    const int bm = blockIdx.y * 128, bn = blockIdx.x * 128;

    const uint32_t sbase = smem_u32(sm);
    const int r0 = tid >> 2, c0 = tid & 3;
    const __half* gsrc[3] = {
        Ahi + (size_t)bm * K, Alo + (size_t)bm * K, B16 + (size_t)bn * K
    };

    float acc[4][4][4] = {};

    const int NS = K / 32;
    for (int s = 0; s < NS; s++) {
        const int k0 = s * 32;
        #pragma unroll
        for (int tile = 0; tile < 3; tile++) {
            const __half* src = gsrc[tile] + (size_t)r0 * K + k0 + c0 * 8;
            uint32_t d = sbase + (tile * TILE_W + r0 * TW + c0 * 4) * 4;
            CP_ASYNC16(d, src);
            CP_ASYNC16(d + 64 * TW * 4, src + (size_t)64 * K);
        }
        CP_COMMIT();
        CP_WAIT0();
        __syncthreads();

        const uint32_t* As  = sm + 0 * TILE_W;
        const uint32_t* Als = sm + 1 * TILE_W;
        const uint32_t* Bs  = sm + 2 * TILE_W;

        #pragma unroll
        for (int kk = 0; kk < 2; kk++) {
            const int kw = kk * 8;
            uint32_t ah[4][4], al[4][4], bb[4][2];
            #pragma unroll
            for (int mf = 0; mf < 4; mf++) {
                const int m0 = wm * 64 + mf * 16;
                const int i0 = (m0 + g) * TW + t + kw;
                const int i8 = (m0 + g + 8) * TW + t + kw;
                ah[mf][0] = As[i0];  ah[mf][1] = As[i8];
                ah[mf][2] = As[i0 + 4]; ah[mf][3] = As[i8 + 4];
                al[mf][0] = Als[i0]; al[mf][1] = Als[i8];
                al[mf][2] = Als[i0 + 4]; al[mf][3] = Als[i8 + 4];
            }
            #pragma unroll
            for (int nf = 0; nf < 4; nf++) {
                const int n0 = wn * 32 + nf * 8;
                const int j0 = (n0 + g) * TW + t + kw;
                bb[nf][0] = Bs[j0];  bb[nf][1] = Bs[j0 + 4];
            }
            #pragma unroll
            for (int mf = 0; mf < 4; mf++)
                #pragma unroll
                for (int nf = 0; nf < 4; nf++) {
                    mma16816h(acc[mf][nf], ah[mf], bb[nf]);
                    mma16816h(acc[mf][nf], al[mf], bb[nf]);
                }
        }
        __syncthreads();
    }

    #pragma unroll
    for (int mf = 0; mf < 4; mf++) {
        const int m = bm + wm * 64 + mf * 16 + g;
        #pragma unroll
        for (int nf = 0; nf < 4; nf++) {
            const int n = bn + wn * 32 + nf * 8 + 2 * t;
            float v0 = acc[mf][nf][0] * scale, v1 = acc[mf][nf][1] * scale;
            float v2 = acc[mf][nf][2] * scale, v3 = acc[mf][nf][3] * scale;
            if (Cf) {
                *(float2*)(Cf + (size_t)m * N + n)       = make_float2(v0, v1);
                *(float2*)(Cf + (size_t)(m + 8) * N + n) = make_float2(v2, v3);
            }
            if (H1 && H2) {
                uint32_t h01, l01, h23, l23;
                split_pack2h(v0, v1, h01, l01);
                split_pack2h(v2, v3, h23, l23);
                *(uint32_t*)(H1 + (size_t)m * N + n)       = h01;
                *(uint32_t*)(H2 + (size_t)m * N + n)       = l01;
                *(uint32_t*)(H1 + (size_t)(m + 8) * N + n) = h23;
                *(uint32_t*)(H2 + (size_t)(m + 8) * N + n) = l23;
            } else if (H1) {
                *(uint32_t*)(H1 + (size_t)m * N + n)       = packh2(v0, v1);
                *(uint32_t*)(H1 + (size_t)(m + 8) * N + n) = packh2(v2, v3);
            }
        }
    }
}

// Batched Q/K/V projection GEMM: grid.z selects tensor set via global symbols.
__global__ __launch_bounds__(256) void gemm_qkv(int M, int N, int K) {
    __shared__ uint32_t sm[3 * TILE_W];
    switch (blockIdx.z) {
        case 0:  gemm_core_h(g_qh, g_ql, g_wq16, nullptr, g_qp, nullptr,
                             0.125f, M, N, K, sm); break;
        case 1:  gemm_core_h(g_kh, g_kl, g_wk16, nullptr, g_kp, nullptr,
                             1.0f, M, N, K, sm); break;
        default: gemm_core_h(g_vh, g_vl, g_wv16, nullptr, g_vp, nullptr,
                             1.0f, M, N, K, sm); break;
    }
}

__global__ __launch_bounds__(256) void gemm_wo(float* __restrict__ Cf,
                                               int M, int N, int K) {
    __shared__ uint32_t sm[3 * TILE_W];
    gemm_core_h(g_ch, g_cl, g_wo16, Cf, nullptr, nullptr, 1.0f, M, N, K, sm);
}

// ---------------------------------------------------------------------------
// Flash attention: 128 queries/block, 8 warps, KV tile = 32, single-buffered.
// QK^T: fp16 Q single x K single (1 MMA). PV: fp16 P single x V single
// (1 MMA). SMEM: K 4608 + V 5120 = 9728 B static.
// ---------------------------------------------------------------------------
#define FKP 72
#define FVP 40

__global__ __launch_bounds__(256) void flash_mma() {
    __shared__ __half Ksh[32 * FKP];
    __shared__ __half Vsh[64 * FVP];

    const int tid = threadIdx.x, wid = tid >> 5, lane = tid & 31;
    const int g = lane >> 2, t = lane & 3;
    const int qt = blockIdx.x, h = blockIdx.y, b = blockIdx.z;
    const int q0 = qt * 128, m0 = wid * 16;

    // Q fragments from global (fp16 single, pre-scaled by 1/8)
    uint32_t qf[4][4];
    {
        const size_t rbase = (size_t)(b * SEQ + q0 + m0 + g) * EMB + h * HD;
        const __half* q0h = g_qp + rbase;
        const __half* q8h = q0h + (size_t)8 * EMB;
        #pragma unroll
        for (int kc = 0; kc < 4; kc++) {
            const int d0 = kc * 16 + 2 * t;
            qf[kc][0] = *(const uint32_t*)(q0h + d0);
            qf[kc][1] = *(const uint32_t*)(q8h + d0);
            qf[kc][2] = *(const uint32_t*)(q0h + d0 + 8);
            qf[kc][3] = *(const uint32_t*)(q8h + d0 + 8);
        }
    }

    float O[8][4] = {};
    float m_g = -1e30f, m_g8 = -1e30f, l_g = 0.f, l_g8 = 0.f;

    const int kr = tid >> 3, kc8 = tid & 7;   // K loader: 32 rows x 8 chunks
    const int vd = tid >> 2, vc = tid & 3;    // V loader: 64 rows x 4 chunks
    const __half* khb = g_kp + (size_t)(b * SEQ) * EMB + h * HD;
    const __half* vhb = g_vt + (size_t)((b * NH + h) * HD) * SEQ;
    const uint32_t sKh = smem_u32(Ksh);
    const uint32_t sVh = smem_u32(Vsh);

    for (int j0 = 0; j0 < SEQ; j0 += 32) {
        {
            const __half* ks = khb + (size_t)(j0 + kr) * EMB + kc8 * 8;
            CP_ASYNC16(sKh + kr * (FKP * 2) + kc8 * 16, ks);
            const __half* vs = vhb + (size_t)vd * SEQ + j0 + vc * 8;
            CP_ASYNC16(sVh + vd * (FVP * 2) + vc * 16, vs);
        }
        CP_COMMIT();
        CP_WAIT0();
        __syncthreads();

        // S = Q K^T  (1 MMA per tile)
        float s[4][4] = {};
        #pragma unroll
        for (int kc = 0; kc < 4; kc++) {
            uint32_t bk[4][2];
            #pragma unroll
            for (int nf = 0; nf < 4; nf++) {
                const int base = (nf * 8 + g) * FKP + kc * 16 + 2 * t;
                bk[nf][0] = *(const uint32_t*)(Ksh + base);
                bk[nf][1] = *(const uint32_t*)(Ksh + base + 8);
            }
            #pragma unroll
            for (int nf = 0; nf < 4; nf++)
                mma16816h(s[nf], qf[kc], bk[nf]);
        }

        // online softmax
        float mx0 = -1e30f, mx8 = -1e30f;
        #pragma unroll
        for (int nf = 0; nf < 4; nf++) {
            mx0 = fmaxf(mx0, fmaxf(s[nf][0], s[nf][1]));
            mx8 = fmaxf(mx8, fmaxf(s[nf][2], s[nf][3]));
        }
        mx0 = fmaxf(mx0, __shfl_xor_sync(0xffffffffu, mx0, 1));
        mx0 = fmaxf(mx0, __shfl_xor_sync(0xffffffffu, mx0, 2));
        mx8 = fmaxf(mx8, __shfl_xor_sync(0xffffffffu, mx8, 1));
        mx8 = fmaxf(mx8, __shfl_xor_sync(0xffffffffu, mx8, 2));
        const float mn_g = fmaxf(m_g, mx0), mn_g8 = fmaxf(m_g8, mx8);
        const float alpha_g = __expf(m_g - mn_g), alpha_g8 = __expf(m_g8 - mn_g8);
        m_g = mn_g; m_g8 = mn_g8;

        float p[4][4];
        float sum0 = 0.f, sum8 = 0.f;
        #pragma unroll
        for (int nf = 0; nf < 4; nf++) {
            p[nf][0] = __expf(s[nf][0] - mn_g);
            p[nf][1] = __expf(s[nf][1] - mn_g);
            p[nf][2] = __expf(s[nf][2] - mn_g8);
            p[nf][3] = __expf(s[nf][3] - mn_g8);
            sum0 += p[nf][0] + p[nf][1];
            sum8 += p[nf][2] + p[nf][3];
        }
        sum0 += __shfl_xor_sync(0xffffffffu, sum0, 1);
        sum0 += __shfl_xor_sync(0xffffffffu, sum0, 2);
        sum8 += __shfl_xor_sync(0xffffffffu, sum8, 1);
        sum8 += __shfl_xor_sync(0xffffffffu, sum8, 2);
        l_g  = l_g  * alpha_g  + sum0;
        l_g8 = l_g8 * alpha_g8 + sum8;

        #pragma unroll
        for (int nf2 = 0; nf2 < 8; nf2++) {
            O[nf2][0] *= alpha_g;  O[nf2][1] *= alpha_g;
            O[nf2][2] *= alpha_g8; O[nf2][3] *= alpha_g8;
        }

        // P fragments: fp16, no split
        uint32_t pf[2][4];
        #pragma unroll
        for (int kc2 = 0; kc2 < 2; kc2++) {
            const int nA = 2 * kc2, nB = 2 * kc2 + 1;
            pf[kc2][0] = packh2(p[nA][0], p[nA][1]);
            pf[kc2][1] = packh2(p[nA][2], p[nA][3]);
            pf[kc2][2] = packh2(p[nB][0], p[nB][1]);
            pf[kc2][3] = packh2(p[nB][2], p[nB][3]);
        }

        // O += P V  (1 MMA per tile)
        #pragma unroll
        for (int nf2 = 0; nf2 < 8; nf2++) {
            #pragma unroll
            for (int kc2 = 0; kc2 < 2; kc2++) {
                const int base = (nf2 * 8 + g) * FVP + kc2 * 16 + 2 * t;
                uint32_t vb[2];
                vb[0] = *(const uint32_t*)(Vsh + base);
                vb[1] = *(const uint32_t*)(Vsh + base + 8);
                mma16816h(O[nf2], pf[kc2], vb);
            }
        }
        __syncthreads();
    }

    const float li_g = 1.0f / l_g, li_g8 = 1.0f / l_g8;
    const size_t row0 = (size_t)(b * SEQ + q0 + m0 + g) * EMB;
    const size_t row8 = row0 + (size_t)8 * EMB;
    #pragma unroll
    for (int nf2 = 0; nf2 < 8; nf2++) {
        const int col = h * HD + nf2 * 8 + 2 * t;
        uint32_t h01, l01, h23, l23;
        split_pack2h(O[nf2][0] * li_g,  O[nf2][1] * li_g,  h01, l01);
        split_pack2h(O[nf2][2] * li_g8, O[nf2][3] * li_g8, h23, l23);
        *(uint32_t*)(g_ch + row0 + col) = h01;
        *(uint32_t*)(g_cl + row0 + col) = l01;
        *(uint32_t*)(g_ch + row8 + col) = h23;
        *(uint32_t*)(g_cl + row8 + col) = l23;
    }
}

// ---------------------------------------------------------------------------
extern "C" void kernel_launch(void* const* d_in, const int* in_sizes, int n_in,
                              void* d_out, int out_size)
{
    const float* Q  = (const float*)d_in[0];
    const float* K  = (const float*)d_in[1];
    const float* V  = (const float*)d_in[2];
    const float* Wq = (const float*)d_in[3];
    const float* Wk = (const float*)d_in[4];
    const float* Wv = (const float*)d_in[5];
    const float* Wo = (const float*)d_in[6];
    float* out = (float*)d_out;

    const int n4 = MROWS * EMB / 4;
    const int sb = 256, sg = (n4 + sb - 1) / sb;
    split_h16_3<<<dim3(sg, 3), sb>>>(Q, K, V, n4);

    dim3 tb(32, 8);
    transpose_w_4<<<dim3(EMB / 32, EMB / 32, 4), tb>>>(Wq, Wk, Wv, Wo);

    gemm_qkv<<<dim3(EMB / 128, MROWS / 128, 3), 256>>>(MROWS, EMB, EMB);

    dim3 vt(SEQ / 32, HD / 32, BATCH * NH);    // (64, 2, 32)
    transpose_v<<<vt, tb>>>();

    dim3 ga(SEQ / 128, NH, BATCH);             // (16, 16, 2)
    flash_mma<<<ga, 256>>>();

    gemm_wo<<<dim3(EMB / 128, MROWS / 128), 256>>>(out, MROWS, EMB, EMB);
}

// round 17
// speedup vs baseline: 2.3998x; 1.3133x over previous
#include <cuda_runtime.h>
#include <cuda_bf16.h>
#include <cuda_fp16.h>
#include <cstdint>
#include <cstring>

#define BATCH 2
#define SEQ   2048
#define EMB   1024
#define NH    16
#define HD    64
#define MROWS (BATCH*SEQ)   // 4096

// ---------------------------------------------------------------------------
// Scratch (static device globals). All kernels reference symbols directly.
// ---------------------------------------------------------------------------
__device__ __half g_q16[MROWS * EMB], g_k16[MROWS * EMB], g_v16[MROWS * EMB];  // inputs, fp16
__device__ __half g_qp [MROWS * EMB];                         // Q proj, fp16, pre-scaled
__device__ __half g_kp [MROWS * EMB];                         // K proj, fp16
__device__ __half g_vp [MROWS * EMB];                         // V proj, fp16
__device__ __half g_vt [MROWS * EMB];                         // fp16 V^T
__device__ __half g_c  [MROWS * EMB];                         // attn out, fp16
__device__ __half g_wq16[EMB * EMB], g_wk16[EMB * EMB];      // weights, fp16, [N][K]
__device__ __half g_wv16[EMB * EMB], g_wo16[EMB * EMB];

// ---------------------------------------------------------------------------
// Helpers
// ---------------------------------------------------------------------------
__device__ __forceinline__ uint32_t smem_u32(const void* p) {
    uint32_t a;
    asm("{ .reg .u64 t; cvta.to.shared.u64 t, %1; cvt.u32.u64 %0, t; }" : "=r"(a) : "l"(p));
    return a;
}

#define CP_ASYNC16(dst, src) \
    asm volatile("cp.async.cg.shared.global [%0], [%1], 16;" :: "r"((uint32_t)(dst)), "l"(src))
#define CP_COMMIT() asm volatile("cp.async.commit_group;" ::: "memory")
#define CP_WAIT0()  asm volatile("cp.async.wait_group 0;" ::: "memory")
#define CP_WAIT1()  asm volatile("cp.async.wait_group 1;" ::: "memory")

// mma.sync m16n8k16 fp16 -> f32
__device__ __forceinline__ void mma16816h(float* c, const uint32_t* a, const uint32_t* b) {
    asm volatile(
        "mma.sync.aligned.m16n8k16.row.col.f32.f16.f16.f32 "
        "{%0,%1,%2,%3}, {%4,%5,%6,%7}, {%8,%9}, {%0,%1,%2,%3};"
        : "+f"(c[0]), "+f"(c[1]), "+f"(c[2]), "+f"(c[3])
        : "r"(a[0]), "r"(a[1]), "r"(a[2]), "r"(a[3]), "r"(b[0]), "r"(b[1]));
}

__device__ __forceinline__ uint32_t packh2(float x0, float x1) {
    __half2 h = __float22half2_rn(make_float2(x0, x1));
    uint32_t u;
    memcpy(&u, &h, 4);
    return u;
}

// ---------------------------------------------------------------------------
// Pre-pass 1: batched fp16 convert of Q,K,V (grid.y in {0,1,2})
// ---------------------------------------------------------------------------
__global__ void cvt_h16_3(const float* __restrict__ Q, const float* __restrict__ K,
                          const float* __restrict__ V, int n4) {
    const int z = blockIdx.y;
    int i = blockIdx.x * blockDim.x + threadIdx.x;
    if (i >= n4) return;
    const float* x;
    __half* o;
    switch (z) {
        case 0:  x = Q; o = g_q16; break;
        case 1:  x = K; o = g_k16; break;
        default: x = V; o = g_v16; break;
    }
    float4 v = ((const float4*)x)[i];
    ((uint2*)o)[i] = make_uint2(packh2(v.x, v.y), packh2(v.z, v.w));
}

// ---------------------------------------------------------------------------
// Pre-pass 2: batched W[K][N] -> Wt fp16 [N][K] (grid.z in {0..3})
// ---------------------------------------------------------------------------
__global__ void transpose_w_4(const float* __restrict__ Wq, const float* __restrict__ Wk,
                              const float* __restrict__ Wv, const float* __restrict__ Wo) {
    __shared__ float t[32][33];
    const float* W;
    __half* T;
    switch (blockIdx.z) {
        case 0:  W = Wq; T = g_wq16; break;
        case 1:  W = Wk; T = g_wk16; break;
        case 2:  W = Wv; T = g_wv16; break;
        default: W = Wo; T = g_wo16; break;
    }
    int x = blockIdx.x * 32 + threadIdx.x;
    int y = blockIdx.y * 32 + threadIdx.y;
    #pragma unroll
    for (int i = 0; i < 32; i += 8)
        t[threadIdx.y + i][threadIdx.x] = W[(size_t)(y + i) * EMB + x];
    __syncthreads();
    int nx = blockIdx.y * 32 + threadIdx.x;
    int ny = blockIdx.x * 32 + threadIdx.y;
    #pragma unroll
    for (int i = 0; i < 32; i += 8)
        T[(size_t)(ny + i) * EMB + nx] = __float2half_rn(t[threadIdx.x][threadIdx.y + i]);
}

// ---------------------------------------------------------------------------
// V transpose (plain fp16): [b*S+s][h*64+d] -> [(b*16+h)*64+d][s]
// ---------------------------------------------------------------------------
__global__ void transpose_v() {
    __shared__ __half a[32][33];
    const int bh = blockIdx.z;
    const int b = bh >> 4, h = bh & 15;
    const int s0 = blockIdx.x * 32, d0 = blockIdx.y * 32;
    const int tx = threadIdx.x, ty = threadIdx.y;
    #pragma unroll
    for (int i = 0; i < 32; i += 8) {
        size_t src = (size_t)(b * SEQ + s0 + ty + i) * EMB + h * HD + d0 + tx;
        a[ty + i][tx] = g_vp[src];
    }
    __syncthreads();
    #pragma unroll
    for (int i = 0; i < 32; i += 8) {
        size_t dst = (size_t)(bh * HD + d0 + ty + i) * SEQ + s0 + tx;
        g_vt[dst] = a[tx][ty + i];
    }
}

// ---------------------------------------------------------------------------
// mma.sync fp16 GEMM core, single term, 2-stage pipelined:
// C = A16[M,K] @ W16[N,K]^T. Block 128x128, BK=32, 256 threads, 8 warps 2x4.
// SMEM: 2 stages x 2 tiles x 128 rows x 20 words = 40960 B static (in caller).
// Epilogue variants: fp32 (Cf) or fp16 single (H1).
// ---------------------------------------------------------------------------
#define TW 20
#define TILE_W (128 * TW)

__device__ __forceinline__ void gemm_core_h1(
    const __half* __restrict__ A16, const __half* __restrict__ B16,
    float* __restrict__ Cf, __half* __restrict__ H1,
    float scale, int M, int N, int K, uint32_t* sm)
{
    const int tid = threadIdx.x;
    const int wid = tid >> 5, lane = tid & 31;
    const int g = lane >> 2, t = lane & 3;
    const int wm = wid & 1, wn = wid >> 1;
    const int bm = blockIdx.y * 128, bn = blockIdx.x * 128;

    const uint32_t sbase = smem_u32(sm);
    const int r0 = tid >> 2, c0 = tid & 3;
    const __half* gsrc[2] = { A16 + (size_t)bm * K, B16 + (size_t)bn * K };

    float acc[4][4][4] = {};

    auto issue = [&](int st, int k0) {
        #pragma unroll
        for (int tile = 0; tile < 2; tile++) {
            const __half* src = gsrc[tile] + (size_t)r0 * K + k0 + c0 * 8;
            uint32_t d = sbase + ((st * 2 + tile) * TILE_W + r0 * TW + c0 * 4) * 4;
            CP_ASYNC16(d, src);
            CP_ASYNC16(d + 64 * TW * 4, src + (size_t)64 * K);
        }
    };

    const int NS = K / 32;
    issue(0, 0);
    CP_COMMIT();

    for (int s = 0; s < NS; s++) {
        if (s + 1 < NS) {
            issue((s + 1) & 1, (s + 1) * 32);
            CP_COMMIT();
            CP_WAIT1();
        } else {
            CP_WAIT0();
        }
        __syncthreads();

        const uint32_t* As = sm + ((s & 1) * 2 + 0) * TILE_W;
        const uint32_t* Bs = sm + ((s & 1) * 2 + 1) * TILE_W;

        #pragma unroll
        for (int kk = 0; kk < 2; kk++) {
            const int kw = kk * 8;
            uint32_t aa[4][4], bb[4][2];
            #pragma unroll
            for (int mf = 0; mf < 4; mf++) {
                const int m0 = wm * 64 + mf * 16;
                const int i0 = (m0 + g) * TW + t + kw;
                const int i8 = (m0 + g + 8) * TW + t + kw;
                aa[mf][0] = As[i0];  aa[mf][1] = As[i8];
                aa[mf][2] = As[i0 + 4]; aa[mf][3] = As[i8 + 4];
            }
            #pragma unroll
            for (int nf = 0; nf < 4; nf++) {
                const int n0 = wn * 32 + nf * 8;
                const int j0 = (n0 + g) * TW + t + kw;
                bb[nf][0] = Bs[j0];  bb[nf][1] = Bs[j0 + 4];
            }
            #pragma unroll
            for (int mf = 0; mf < 4; mf++)
                #pragma unroll
                for (int nf = 0; nf < 4; nf++)
                    mma16816h(acc[mf][nf], aa[mf], bb[nf]);
        }
        __syncthreads();
    }

    #pragma unroll
    for (int mf = 0; mf < 4; mf++) {
        const int m = bm + wm * 64 + mf * 16 + g;
        #pragma unroll
        for (int nf = 0; nf < 4; nf++) {
            const int n = bn + wn * 32 + nf * 8 + 2 * t;
            float v0 = acc[mf][nf][0] * scale, v1 = acc[mf][nf][1] * scale;
            float v2 = acc[mf][nf][2] * scale, v3 = acc[mf][nf][3] * scale;
            if (Cf) {
                *(float2*)(Cf + (size_t)m * N + n)       = make_float2(v0, v1);
                *(float2*)(Cf + (size_t)(m + 8) * N + n) = make_float2(v2, v3);
            } else {
                *(uint32_t*)(H1 + (size_t)m * N + n)       = packh2(v0, v1);
                *(uint32_t*)(H1 + (size_t)(m + 8) * N + n) = packh2(v2, v3);
            }
        }
    }
}

// Batched Q/K/V projection GEMM: grid.z selects tensor set via global symbols.
__global__ __launch_bounds__(256) void gemm_qkv(int M, int N, int K) {
    __shared__ uint32_t sm[4 * TILE_W];   // 40960 B
    switch (blockIdx.z) {
        case 0:  gemm_core_h1(g_q16, g_wq16, nullptr, g_qp, 0.125f, M, N, K, sm); break;
        case 1:  gemm_core_h1(g_k16, g_wk16, nullptr, g_kp, 1.0f,   M, N, K, sm); break;
        default: gemm_core_h1(g_v16, g_wv16, nullptr, g_vp, 1.0f,   M, N, K, sm); break;
    }
}

__global__ __launch_bounds__(256) void gemm_wo(float* __restrict__ Cf,
                                               int M, int N, int K) {
    __shared__ uint32_t sm[4 * TILE_W];
    gemm_core_h1(g_c, g_wo16, Cf, nullptr, 1.0f, M, N, K, sm);
}

// ---------------------------------------------------------------------------
// Flash attention: 128 queries/block, 8 warps, KV tile = 32, single-buffered.
// QK^T: fp16 Q x K (1 MMA). PV: fp16 P x V (1 MMA).
// SMEM: K 4608 + V 5120 = 9728 B static.
// ---------------------------------------------------------------------------
#define FKP 72
#define FVP 40

__global__ __launch_bounds__(256) void flash_mma() {
    __shared__ __half Ksh[32 * FKP];
    __shared__ __half Vsh[64 * FVP];

    const int tid = threadIdx.x, wid = tid >> 5, lane = tid & 31;
    const int g = lane >> 2, t = lane & 3;
    const int qt = blockIdx.x, h = blockIdx.y, b = blockIdx.z;
    const int q0 = qt * 128, m0 = wid * 16;

    // Q fragments from global (fp16, pre-scaled by 1/8)
    uint32_t qf[4][4];
    {
        const size_t rbase = (size_t)(b * SEQ + q0 + m0 + g) * EMB + h * HD;
        const __half* q0h = g_qp + rbase;
        const __half* q8h = q0h + (size_t)8 * EMB;
        #pragma unroll
        for (int kc = 0; kc < 4; kc++) {
            const int d0 = kc * 16 + 2 * t;
            qf[kc][0] = *(const uint32_t*)(q0h + d0);
            qf[kc][1] = *(const uint32_t*)(q8h + d0);
            qf[kc][2] = *(const uint32_t*)(q0h + d0 + 8);
            qf[kc][3] = *(const uint32_t*)(q8h + d0 + 8);
        }
    }

    float O[8][4] = {};
    float m_g = -1e30f, m_g8 = -1e30f, l_g = 0.f, l_g8 = 0.f;

    const int kr = tid >> 3, kc8 = tid & 7;
    const int vd = tid >> 2, vc = tid & 3;
    const __half* khb = g_kp + (size_t)(b * SEQ) * EMB + h * HD;
    const __half* vhb = g_vt + (size_t)((b * NH + h) * HD) * SEQ;
    const uint32_t sKh = smem_u32(Ksh);
    const uint32_t sVh = smem_u32(Vsh);

    for (int j0 = 0; j0 < SEQ; j0 += 32) {
        {
            const __half* ks = khb + (size_t)(j0 + kr) * EMB + kc8 * 8;
            CP_ASYNC16(sKh + kr * (FKP * 2) + kc8 * 16, ks);
            const __half* vs = vhb + (size_t)vd * SEQ + j0 + vc * 8;
            CP_ASYNC16(sVh + vd * (FVP * 2) + vc * 16, vs);
        }
        CP_COMMIT();
        CP_WAIT0();
        __syncthreads();

        // S = Q K^T
        float s[4][4] = {};
        #pragma unroll
        for (int kc = 0; kc < 4; kc++) {
            uint32_t bk[4][2];
            #pragma unroll
            for (int nf = 0; nf < 4; nf++) {
                const int base = (nf * 8 + g) * FKP + kc * 16 + 2 * t;
                bk[nf][0] = *(const uint32_t*)(Ksh + base);
                bk[nf][1] = *(const uint32_t*)(Ksh + base + 8);
            }
            #pragma unroll
            for (int nf = 0; nf < 4; nf++)
                mma16816h(s[nf], qf[kc], bk[nf]);
        }

        // online softmax
        float mx0 = -1e30f, mx8 = -1e30f;
        #pragma unroll
        for (int nf = 0; nf < 4; nf++) {
            mx0 = fmaxf(mx0, fmaxf(s[nf][0], s[nf][1]));
            mx8 = fmaxf(mx8, fmaxf(s[nf][2], s[nf][3]));
        }
        mx0 = fmaxf(mx0, __shfl_xor_sync(0xffffffffu, mx0, 1));
        mx0 = fmaxf(mx0, __shfl_xor_sync(0xffffffffu, mx0, 2));
        mx8 = fmaxf(mx8, __shfl_xor_sync(0xffffffffu, mx8, 1));
        mx8 = fmaxf(mx8, __shfl_xor_sync(0xffffffffu, mx8, 2));
        const float mn_g = fmaxf(m_g, mx0), mn_g8 = fmaxf(m_g8, mx8);
        const float alpha_g = __expf(m_g - mn_g), alpha_g8 = __expf(m_g8 - mn_g8);
        m_g = mn_g; m_g8 = mn_g8;

        float p[4][4];
        float sum0 = 0.f, sum8 = 0.f;
        #pragma unroll
        for (int nf = 0; nf < 4; nf++) {
            p[nf][0] = __expf(s[nf][0] - mn_g);
            p[nf][1] = __expf(s[nf][1] - mn_g);
            p[nf][2] = __expf(s[nf][2] - mn_g8);
            p[nf][3] = __expf(s[nf][3] - mn_g8);
            sum0 += p[nf][0] + p[nf][1];
            sum8 += p[nf][2] + p[nf][3];
        }
        sum0 += __shfl_xor_sync(0xffffffffu, sum0, 1);
        sum0 += __shfl_xor_sync(0xffffffffu, sum0, 2);
        sum8 += __shfl_xor_sync(0xffffffffu, sum8, 1);
        sum8 += __shfl_xor_sync(0xffffffffu, sum8, 2);
        l_g  = l_g  * alpha_g  + sum0;
        l_g8 = l_g8 * alpha_g8 + sum8;

        #pragma unroll
        for (int nf2 = 0; nf2 < 8; nf2++) {
            O[nf2][0] *= alpha_g;  O[nf2][1] *= alpha_g;
            O[nf2][2] *= alpha_g8; O[nf2][3] *= alpha_g8;
        }

        // P fragments: fp16
        uint32_t pf[2][4];
        #pragma unroll
        for (int kc2 = 0; kc2 < 2; kc2++) {
            const int nA = 2 * kc2, nB = 2 * kc2 + 1;
            pf[kc2][0] = packh2(p[nA][0], p[nA][1]);
            pf[kc2][1] = packh2(p[nA][2], p[nA][3]);
            pf[kc2][2] = packh2(p[nB][0], p[nB][1]);
            pf[kc2][3] = packh2(p[nB][2], p[nB][3]);
        }

        // O += P V
        #pragma unroll
        for (int nf2 = 0; nf2 < 8; nf2++) {
            #pragma unroll
            for (int kc2 = 0; kc2 < 2; kc2++) {
                const int base = (nf2 * 8 + g) * FVP + kc2 * 16 + 2 * t;
                uint32_t vb[2];
                vb[0] = *(const uint32_t*)(Vsh + base);
                vb[1] = *(const uint32_t*)(Vsh + base + 8);
                mma16816h(O[nf2], pf[kc2], vb);
            }
        }
        __syncthreads();
    }

    // epilogue: normalize, fp16 single out
    const float li_g = 1.0f / l_g, li_g8 = 1.0f / l_g8;
    const size_t row0 = (size_t)(b * SEQ + q0 + m0 + g) * EMB;
    const size_t row8 = row0 + (size_t)8 * EMB;
    #pragma unroll
    for (int nf2 = 0; nf2 < 8; nf2++) {
        const int col = h * HD + nf2 * 8 + 2 * t;
        *(uint32_t*)(g_c + row0 + col) = packh2(O[nf2][0] * li_g,  O[nf2][1] * li_g);
        *(uint32_t*)(g_c + row8 + col) = packh2(O[nf2][2] * li_g8, O[nf2][3] * li_g8);
    }
}

// ---------------------------------------------------------------------------
extern "C" void kernel_launch(void* const* d_in, const int* in_sizes, int n_in,
                              void* d_out, int out_size)
{
    const float* Q  = (const float*)d_in[0];
    const float* K  = (const float*)d_in[1];
    const float* V  = (const float*)d_in[2];
    const float* Wq = (const float*)d_in[3];
    const float* Wk = (const float*)d_in[4];
    const float* Wv = (const float*)d_in[5];
    const float* Wo = (const float*)d_in[6];
    float* out = (float*)d_out;

    const int n4 = MROWS * EMB / 4;
    const int sb = 256, sg = (n4 + sb - 1) / sb;
    cvt_h16_3<<<dim3(sg, 3), sb>>>(Q, K, V, n4);

    dim3 tb(32, 8);
    transpose_w_4<<<dim3(EMB / 32, EMB / 32, 4), tb>>>(Wq, Wk, Wv, Wo);

    gemm_qkv<<<dim3(EMB / 128, MROWS / 128, 3), 256>>>(MROWS, EMB, EMB);

    dim3 vt(SEQ / 32, HD / 32, BATCH * NH);    // (64, 2, 32)
    transpose_v<<<vt, tb>>>();

    dim3 ga(SEQ / 128, NH, BATCH);             // (16, 16, 2)
    flash_mma<<<ga, 256>>>();

    gemm_wo<<<dim3(EMB / 128, MROWS / 128), 256>>>(out, MROWS, EMB, EMB);
}